// round 1
// baseline (speedup 1.0000x reference)
#include <cuda_runtime.h>
#include <math.h>

#define H   96
#define W   96
#define HW  9216
#define HP  98
#define HPWP 9604
#define CIN 512
#define C1  256
#define C2  64
#define BATCH 2
#define NS  9
#define COFF 28
#define EPSV 1e-5f

// ---------------- scratch (static device memory; no allocs) ----------------
__device__ float g_f1[BATCH * C1 * HW];        // conv1 output (pre-BN2)
__device__ float g_f2[BATCH * C1 * HPWP];      // BN2-applied, zero-padded feature map
__device__ float g_off[BATCH * COFF * HW];     // 0..17 raw offsets, 18..26 sigmoid mod, 27 = 2*sigmoid scale
__device__ float g_wT1[CIN * C1];              // conv1 weights transposed [ci][co]
__device__ float g_wT6[C1 * NS * 32];          // offset conv weights [k=ci*9+r][co(28 padded to 32)]
__device__ float g_biasC[32];                  // combined offset-conv bias
__device__ float g_wT7[C1 * NS * C2];          // dconv weights [k][o]
__device__ float g_a1[CIN], g_b1[CIN];         // BN1 scale/shift
__device__ float g_a2[C1],  g_b2[C1];          // BN2 scale/shift

// ---------------- weight prep (transpose once) ----------------
__global__ void prep_kernel(const float* __restrict__ w1,
                            const float* __restrict__ pw, const float* __restrict__ pb,
                            const float* __restrict__ mw, const float* __restrict__ mb,
                            const float* __restrict__ dw, const float* __restrict__ db,
                            const float* __restrict__ w7) {
    int i = blockIdx.x * blockDim.x + threadIdx.x;
    if (i < CIN * C1) {
        int ci = i / C1, co = i % C1;
        g_wT1[i] = w1[co * CIN + ci];
    }
    if (i < C1 * NS * 32) {
        int k = i / 32, co = i % 32;
        int ci = k / NS, r = k % NS;
        float v = 0.f;
        if (co < 18)       v = pw[(co * C1 + ci) * NS + r];
        else if (co < 27)  v = mw[((co - 18) * C1 + ci) * NS + r];
        else if (co == 27) v = dw[ci * NS + r];
        g_wT6[i] = v;
    }
    if (i < C1 * NS * C2) {
        int k = i / C2, o = i % C2;
        int ci = k / NS, r = k % NS;
        g_wT7[i] = w7[(o * C1 + ci) * NS + r];
    }
    if (i < 32) {
        float v = 0.f;
        if (i < 18)       v = pb[i];
        else if (i < 27)  v = mb[i - 18];
        else if (i == 27) v = db[0];
        g_biasC[i] = v;
    }
}

// ---------------- BN stats (train mode: batch statistics) ----------------
__device__ __forceinline__ void bn_reduce(float s, float s2, float* sh,
                                          float gamma, float beta,
                                          float* a_out, float* b_out, int c) {
    sh[threadIdx.x] = s;
    sh[256 + threadIdx.x] = s2;
    __syncthreads();
    for (int st = 128; st > 0; st >>= 1) {
        if (threadIdx.x < st) {
            sh[threadIdx.x]       += sh[threadIdx.x + st];
            sh[256 + threadIdx.x] += sh[256 + threadIdx.x + st];
        }
        __syncthreads();
    }
    if (threadIdx.x == 0) {
        const float inv = 1.f / (float)(BATCH * HW);
        float mean = sh[0] * inv;
        float var  = sh[256] * inv - mean * mean;
        float a = gamma / sqrtf(var + EPSV);
        a_out[c] = a;
        b_out[c] = beta - mean * a;
    }
}

__global__ void bn1_stats_kernel(const float* __restrict__ x,
                                 const float* __restrict__ gamma,
                                 const float* __restrict__ beta) {
    __shared__ float sh[512];
    int c = blockIdx.x;
    float s = 0.f, s2 = 0.f;
    for (int e = threadIdx.x; e < BATCH * HW; e += 256) {
        int bb = e / HW, p = e % HW;
        float v = x[(bb * CIN + c) * HW + p];
        s += v; s2 += v * v;
    }
    bn_reduce(s, s2, sh, gamma[c], beta[c], g_a1, g_b1, c);
}

__global__ void bn2_stats_kernel(const float* __restrict__ gamma,
                                 const float* __restrict__ beta) {
    __shared__ float sh[512];
    int c = blockIdx.x;
    float s = 0.f, s2 = 0.f;
    for (int e = threadIdx.x; e < BATCH * HW; e += 256) {
        int bb = e / HW, p = e % HW;
        float v = g_f1[(bb * C1 + c) * HW + p];
        s += v; s2 += v * v;
    }
    bn_reduce(s, s2, sh, gamma[c], beta[c], g_a2, g_b2, c);
}

// ---------------- conv1: 1x1 GEMM with fused BN1+ReLU on the B load --------
// grid (144, 4, 2), block 256. Tile 64(co) x 64(px), K chunks of 32.
__global__ __launch_bounds__(256) void conv1_kernel(const float* __restrict__ x,
                                                    const float* __restrict__ bias) {
    __shared__ float Ws[32][64];
    __shared__ float Bs[32][64];
    const int bz  = blockIdx.z;
    const int p0  = blockIdx.x * 64;
    const int cob = blockIdx.y * 64;
    const int t   = threadIdx.x;
    const int co0 = (t / 16) * 4;
    const int px0 = (t % 16) * 4;
    float acc[4][4] = {};

    for (int k0 = 0; k0 < CIN; k0 += 32) {
        #pragma unroll
        for (int i = 0; i < 8; i++) {
            int e = t + i * 256;
            int kk = e >> 6, o = e & 63;
            Ws[kk][o] = g_wT1[(k0 + kk) * C1 + cob + o];
        }
        #pragma unroll
        for (int i = 0; i < 8; i++) {
            int e = t + i * 256;
            int kk = e >> 6, j = e & 63;
            int ci = k0 + kk;
            float v = x[(bz * CIN + ci) * HW + p0 + j];
            Bs[kk][j] = fmaxf(fmaf(g_a1[ci], v, g_b1[ci]), 0.f);
        }
        __syncthreads();
        #pragma unroll
        for (int kk = 0; kk < 32; kk++) {
            float4 a4 = *(const float4*)(&Ws[kk][co0]);
            float4 b4 = *(const float4*)(&Bs[kk][px0]);
            float aa[4] = {a4.x, a4.y, a4.z, a4.w};
            float bb[4] = {b4.x, b4.y, b4.z, b4.w};
            #pragma unroll
            for (int ii = 0; ii < 4; ii++)
                #pragma unroll
                for (int jj = 0; jj < 4; jj++)
                    acc[ii][jj] = fmaf(aa[ii], bb[jj], acc[ii][jj]);
        }
        __syncthreads();
    }
    #pragma unroll
    for (int ii = 0; ii < 4; ii++) {
        int co = cob + co0 + ii;
        float bv = bias[co];
        #pragma unroll
        for (int jj = 0; jj < 4; jj++)
            g_f1[(bz * C1 + co) * HW + p0 + px0 + jj] = acc[ii][jj] + bv;
    }
}

// ---------------- BN2 apply + zero pad into g_f2 ----------------
__global__ void pad_bn2_kernel() {
    int i = blockIdx.x * blockDim.x + threadIdx.x;
    if (i >= BATCH * C1 * HPWP) return;
    int pp = i % HPWP;
    int bc = i / HPWP;
    int c  = bc % C1;
    int y  = pp / HP, xx = pp % HP;
    float v = 0.f;
    if (y >= 1 && y <= H && xx >= 1 && xx <= W)
        v = fmaf(g_a2[c], g_f1[bc * HW + (y - 1) * W + (xx - 1)], g_b2[c]);
    g_f2[i] = v;
}

// ---------------- offset/mod/dilation conv: implicit-im2col GEMM ----------
// grid (144, 1, 2), block 256. Tile 32(co,28 used) x 64(px), K=2304 chunks of 36.
__global__ __launch_bounds__(256) void offconv_kernel() {
    __shared__ float Ws[36][32];
    __shared__ float Bs[36][64];
    const int bz  = blockIdx.z;
    const int p0  = blockIdx.x * 64;
    const int t   = threadIdx.x;
    const int co0 = (t / 16) * 2;
    const int px0 = (t % 16) * 4;
    const float* __restrict__ f2b = g_f2 + bz * C1 * HPWP;
    float acc[2][4] = {};

    for (int c0 = 0; c0 < C1; c0 += 4) {
        const int k0 = c0 * NS;
        #pragma unroll
        for (int i = 0; i < 5; i++) {
            int e = t + i * 256;
            if (e < 36 * 32) {
                int kk = e >> 5, o = e & 31;
                Ws[kk][o] = g_wT6[(k0 + kk) * 32 + o];
            }
        }
        #pragma unroll
        for (int i = 0; i < 9; i++) {
            int e = t + i * 256;
            int kk = e >> 6, j = e & 63;
            int k = k0 + kk;
            int ci = k / NS, r = k % NS;
            int p = p0 + j;
            int py = p / W, px = p % W;
            Bs[kk][j] = f2b[ci * HPWP + (py + r / 3) * HP + (px + r % 3)];
        }
        __syncthreads();
        #pragma unroll
        for (int kk = 0; kk < 36; kk++) {
            float2 a2v = *(const float2*)(&Ws[kk][co0]);
            float4 b4  = *(const float4*)(&Bs[kk][px0]);
            float aa[2] = {a2v.x, a2v.y};
            float bb[4] = {b4.x, b4.y, b4.z, b4.w};
            #pragma unroll
            for (int ii = 0; ii < 2; ii++)
                #pragma unroll
                for (int jj = 0; jj < 4; jj++)
                    acc[ii][jj] = fmaf(aa[ii], bb[jj], acc[ii][jj]);
        }
        __syncthreads();
    }
    #pragma unroll
    for (int ii = 0; ii < 2; ii++) {
        int co = co0 + ii;
        if (co >= COFF) continue;
        float bv = g_biasC[co];
        #pragma unroll
        for (int jj = 0; jj < 4; jj++) {
            float v = acc[ii][jj] + bv;
            if (co >= 18 && co < 27)      v = 1.f / (1.f + expf(-v));   // modulation
            else if (co == 27)            v = 2.f / (1.f + expf(-v));   // dilation scale
            g_off[(bz * COFF + co) * HW + p0 + px0 + jj] = v;
        }
    }
}

// ---------------- deform: bilinear gather + contraction GEMM ----------------
// grid (144, 1, 2), block 256. Tile 64(o) x 64(px), K=2304 chunks of 36.
__global__ __launch_bounds__(256) void deform_kernel(float* __restrict__ out) {
    __shared__ float gw[576][4];   // bilinear weights * modulation
    __shared__ int   gi[576][4];   // clamped plane indices
    __shared__ float Ws[36][64];
    __shared__ float Bs[36][64];
    const int bz = blockIdx.z;
    const int p0 = blockIdx.x * 64;
    const int t  = threadIdx.x;
    const float* __restrict__ offb = g_off + bz * COFF * HW;
    const float* __restrict__ f2b  = g_f2 + bz * C1 * HPWP;

    // Phase A: per (pixel, n) sampling geometry (576 samples)
    for (int e = t; e < 576; e += 256) {
        int j = e / NS, n = e % NS;
        int p = p0 + j;
        int row = p / W, col = p % W;
        float s  = offb[27 * HW + p];
        float m  = offb[(18 + n) * HW + p];
        float ox = offb[n * HW + p];
        float oy = offb[(9 + n) * HW + p];
        float fpx = (float)(row + 1) + 6.f * s * (float)(n / 3 - 1) + ox;
        float fpy = (float)(col + 1) + 6.f * s * (float)(n % 3 - 1) + oy;
        float fx = floorf(fpx), fy = floorf(fpy);
        float qxl = fminf(fmaxf(fx,       0.f), 97.f);
        float qxr = fminf(fmaxf(fx + 1.f, 0.f), 97.f);
        float qyl = fminf(fmaxf(fy,       0.f), 97.f);
        float qyr = fminf(fmaxf(fy + 1.f, 0.f), 97.f);
        float pxc = fminf(fmaxf(fpx, 0.f), 97.f);
        float pyc = fminf(fmaxf(fpy, 0.f), 97.f);
        float wxl = 1.f + (qxl - pxc), wxr = 1.f - (qxr - pxc);
        float wyl = 1.f + (qyl - pyc), wyr = 1.f - (qyr - pyc);
        gw[e][0] = wxl * wyl * m;   // lt
        gw[e][1] = wxr * wyr * m;   // rb
        gw[e][2] = wxl * wyr * m;   // lb
        gw[e][3] = wxr * wyl * m;   // rt
        int ixl = (int)qxl * HP, ixr = (int)qxr * HP;
        int iyl = (int)qyl,      iyr = (int)qyr;
        gi[e][0] = ixl + iyl;
        gi[e][1] = ixr + iyr;
        gi[e][2] = ixl + iyr;
        gi[e][3] = ixr + iyl;
    }
    __syncthreads();

    const int co0 = (t / 16) * 4;
    const int px0 = (t % 16) * 4;
    float acc[4][4] = {};

    for (int c0 = 0; c0 < C1; c0 += 4) {
        const int k0 = c0 * NS;
        #pragma unroll
        for (int i = 0; i < 9; i++) {
            int e = t + i * 256;
            int kk = e >> 6, o = e & 63;
            Ws[kk][o] = g_wT7[(k0 + kk) * C2 + o];
        }
        #pragma unroll
        for (int i = 0; i < 9; i++) {
            int e = t + i * 256;
            int kk = e >> 6, j = e & 63;
            int k = k0 + kk;
            int ci = k / NS, n = k % NS;
            int sm = j * NS + n;
            const float* pl = f2b + ci * HPWP;
            float v = gw[sm][0] * pl[gi[sm][0]]
                    + gw[sm][1] * pl[gi[sm][1]]
                    + gw[sm][2] * pl[gi[sm][2]]
                    + gw[sm][3] * pl[gi[sm][3]];
            Bs[kk][j] = v;
        }
        __syncthreads();
        #pragma unroll
        for (int kk = 0; kk < 36; kk++) {
            float4 a4 = *(const float4*)(&Ws[kk][co0]);
            float4 b4 = *(const float4*)(&Bs[kk][px0]);
            float aa[4] = {a4.x, a4.y, a4.z, a4.w};
            float bb[4] = {b4.x, b4.y, b4.z, b4.w};
            #pragma unroll
            for (int ii = 0; ii < 4; ii++)
                #pragma unroll
                for (int jj = 0; jj < 4; jj++)
                    acc[ii][jj] = fmaf(aa[ii], bb[jj], acc[ii][jj]);
        }
        __syncthreads();
    }
    #pragma unroll
    for (int ii = 0; ii < 4; ii++)
        #pragma unroll
        for (int jj = 0; jj < 4; jj++)
            out[(bz * C2 + co0 + ii) * HW + p0 + px0 + jj] = acc[ii][jj];
}

// ---------------- launch ----------------
extern "C" void kernel_launch(void* const* d_in, const int* in_sizes, int n_in,
                              void* d_out, int out_size) {
    const float* x     = (const float*)d_in[0];
    const float* bn1_g = (const float*)d_in[1];
    const float* bn1_b = (const float*)d_in[2];
    const float* w1    = (const float*)d_in[3];
    const float* b1    = (const float*)d_in[4];
    const float* bn2_g = (const float*)d_in[5];
    const float* bn2_b = (const float*)d_in[6];
    const float* pw    = (const float*)d_in[7];
    const float* pb    = (const float*)d_in[8];
    const float* mw    = (const float*)d_in[9];
    const float* mb    = (const float*)d_in[10];
    const float* dw    = (const float*)d_in[11];
    const float* db    = (const float*)d_in[12];
    const float* w7    = (const float*)d_in[13];
    float* out = (float*)d_out;

    prep_kernel<<<(C1 * NS * C2 + 255) / 256, 256>>>(w1, pw, pb, mw, mb, dw, db, w7);
    bn1_stats_kernel<<<CIN, 256>>>(x, bn1_g, bn1_b);
    conv1_kernel<<<dim3(HW / 64, C1 / 64, BATCH), 256>>>(x, b1);
    bn2_stats_kernel<<<C1, 256>>>(bn2_g, bn2_b);
    pad_bn2_kernel<<<(BATCH * C1 * HPWP + 255) / 256, 256>>>();
    offconv_kernel<<<dim3(HW / 64, 1, BATCH), 256>>>();
    deform_kernel<<<dim3(HW / 64, 1, BATCH), 256>>>(out);
}

// round 3
// speedup vs baseline: 1.2744x; 1.2744x over previous
#include <cuda_runtime.h>
#include <cuda_bf16.h>
#include <math.h>

#define H   96
#define W   96
#define HW  9216
#define HP  98
#define HPWP 9604
#define CIN 512
#define C1  256
#define C2  64
#define BATCH 2
#define NS  9
#define COFF 28
#define KTOT (C1*NS)
#define EPSV 1e-5f

#define WPIT 40
#define BPIT128 136
#define BPIT64  72

// ---------------- scratch ----------------
__device__ float g_f1[BATCH * C1 * HW];
__device__ float g_f2[BATCH * C1 * HPWP];
__device__ float g_off[BATCH * COFF * HW];
__device__ float g_a1[CIN];
__device__ float g_b1[CIN];
__device__ float g_a2[C1];
__device__ float g_b2[C1];
__device__ float g_biasC[32];
__device__ __nv_bfloat16 g_w1h[C1 * CIN];
__device__ __nv_bfloat16 g_w1l[C1 * CIN];
__device__ __nv_bfloat16 g_w6h[32 * KTOT];
__device__ __nv_bfloat16 g_w6l[32 * KTOT];
__device__ __nv_bfloat16 g_w7h[C2 * KTOT];
__device__ __nv_bfloat16 g_w7l[C2 * KTOT];

// ---------------- helpers ----------------
__device__ __forceinline__ void splitf(float v, __nv_bfloat16* hp, __nv_bfloat16* lp) {
    __nv_bfloat16 hb = __float2bfloat16(v);
    *hp = hb;
    *lp = __float2bfloat16(v - __bfloat162float(hb));
}

__device__ __forceinline__ unsigned smaddr(const void* p) {
    return (unsigned)__cvta_generic_to_shared(p);
}

__device__ __forceinline__ void ldsm4(unsigned* r, unsigned a) {
    asm volatile("ldmatrix.sync.aligned.m8n8.x4.shared.b16 {%0,%1,%2,%3}, [%4];"
                 : "=r"(r[0]), "=r"(r[1]), "=r"(r[2]), "=r"(r[3])
                 : "r"(a));
}

__device__ __forceinline__ void ldsm4t(unsigned* r, unsigned a) {
    asm volatile("ldmatrix.sync.aligned.m8n8.x4.trans.shared.b16 {%0,%1,%2,%3}, [%4];"
                 : "=r"(r[0]), "=r"(r[1]), "=r"(r[2]), "=r"(r[3])
                 : "r"(a));
}

__device__ __forceinline__ void mma16816(float* c, const unsigned* a, const unsigned* b) {
    asm volatile("mma.sync.aligned.m16n8k16.row.col.f32.bf16.bf16.f32 "
                 "{%0,%1,%2,%3}, {%4,%5,%6,%7}, {%8,%9}, {%0,%1,%2,%3};"
                 : "+f"(c[0]), "+f"(c[1]), "+f"(c[2]), "+f"(c[3])
                 : "r"(a[0]), "r"(a[1]), "r"(a[2]), "r"(a[3]), "r"(b[0]), "r"(b[1]));
}

// load one 16xK16 A fragment (hi) at [row0][kb] from pitched smem
__device__ __forceinline__ void load_a_frag(unsigned* a, const __nv_bfloat16* base,
                                            int pitch, int row0, int kb, int lane) {
    const __nv_bfloat16* p = base + (row0 + (lane & 15)) * pitch + kb + ((lane >> 4) * 8);
    ldsm4(a, smaddr(p));
}

// load one K16 x N16 B fragment pair (two n8 frags) from [k][n] pitched smem
__device__ __forceinline__ void load_b_frag(unsigned b0[2], unsigned b1[2],
                                            const __nv_bfloat16* base,
                                            int pitch, int kb, int n0, int lane) {
    unsigned tmp[4];
    const __nv_bfloat16* p = base + (kb + (lane & 15)) * pitch + n0 + ((lane >> 4) * 8);
    ldsm4t(tmp, smaddr(p));
    b0[0] = tmp[0];
    b0[1] = tmp[1];
    b1[0] = tmp[2];
    b1[1] = tmp[3];
}

// ---------------- weight prep ----------------
__global__ void prep_kernel(const float* __restrict__ w1,
                            const float* __restrict__ pw, const float* __restrict__ pb,
                            const float* __restrict__ mw, const float* __restrict__ mb,
                            const float* __restrict__ dw, const float* __restrict__ db,
                            const float* __restrict__ w7) {
    int i = blockIdx.x * blockDim.x + threadIdx.x;
    if (i < C1 * CIN) {
        splitf(w1[i], &g_w1h[i], &g_w1l[i]);
    }
    if (i < 32 * KTOT) {
        int co = i / KTOT;
        int k = i % KTOT;
        int r = k / C1;
        int ci = k % C1;
        float v = 0.f;
        if (co < 18) {
            v = pw[(co * C1 + ci) * NS + r];
        } else if (co < 27) {
            v = mw[((co - 18) * C1 + ci) * NS + r];
        } else if (co == 27) {
            v = dw[ci * NS + r];
        }
        splitf(v, &g_w6h[i], &g_w6l[i]);
    }
    if (i < C2 * KTOT) {
        int o = i / KTOT;
        int k = i % KTOT;
        int n = k / C1;
        int ci = k % C1;
        splitf(w7[(o * C1 + ci) * NS + n], &g_w7h[i], &g_w7l[i]);
    }
    if (i < 32) {
        float v = 0.f;
        if (i < 18) {
            v = pb[i];
        } else if (i < 27) {
            v = mb[i - 18];
        } else if (i == 27) {
            v = db[0];
        }
        g_biasC[i] = v;
    }
}

// ---------------- BN stats ----------------
__device__ __forceinline__ void bn_reduce(float s, float s2, float* sh,
                                          float gamma, float beta,
                                          float* a_out, float* b_out, int c) {
    sh[threadIdx.x] = s;
    sh[256 + threadIdx.x] = s2;
    __syncthreads();
    for (int st = 128; st > 0; st >>= 1) {
        if (threadIdx.x < st) {
            sh[threadIdx.x] += sh[threadIdx.x + st];
            sh[256 + threadIdx.x] += sh[256 + threadIdx.x + st];
        }
        __syncthreads();
    }
    if (threadIdx.x == 0) {
        const float inv = 1.f / (float)(BATCH * HW);
        float mean = sh[0] * inv;
        float var = sh[256] * inv - mean * mean;
        float a = gamma / sqrtf(var + EPSV);
        a_out[c] = a;
        b_out[c] = beta - mean * a;
    }
}

__global__ void bn1_stats_kernel(const float* __restrict__ x,
                                 const float* __restrict__ gamma,
                                 const float* __restrict__ beta) {
    __shared__ float sh[512];
    int c = blockIdx.x;
    float s = 0.f;
    float s2 = 0.f;
    for (int e = threadIdx.x; e < BATCH * HW; e += 256) {
        int bb = e / HW;
        int p = e % HW;
        float v = x[(bb * CIN + c) * HW + p];
        s += v;
        s2 += v * v;
    }
    bn_reduce(s, s2, sh, gamma[c], beta[c], g_a1, g_b1, c);
}

__global__ void bn2_stats_kernel(const float* __restrict__ gamma,
                                 const float* __restrict__ beta) {
    __shared__ float sh[512];
    int c = blockIdx.x;
    float s = 0.f;
    float s2 = 0.f;
    for (int e = threadIdx.x; e < BATCH * HW; e += 256) {
        int bb = e / HW;
        int p = e % HW;
        float v = g_f1[(bb * C1 + c) * HW + p];
        s += v;
        s2 += v * v;
    }
    bn_reduce(s, s2, sh, gamma[c], beta[c], g_a2, g_b2, c);
}

// ---------------- conv1: 64(co) x 128(px), tensor-core ----------------
__global__ __launch_bounds__(256) void conv1_kernel(const float* __restrict__ x,
                                                    const float* __restrict__ bias) {
    __shared__ __nv_bfloat16 Ah[64][WPIT];
    __shared__ __nv_bfloat16 Al[64][WPIT];
    __shared__ __nv_bfloat16 Bh[32][BPIT128];
    __shared__ __nv_bfloat16 Bl[32][BPIT128];
    const int bz = blockIdx.z;
    const int p0 = blockIdx.x * 128;
    const int cob = blockIdx.y * 64;
    const int t = threadIdx.x;
    const int lane = t & 31;
    const int wid = t >> 5;
    const int m0 = (wid >> 2) * 32;
    const int n0 = (wid & 3) * 32;
    const float* __restrict__ xb = x + (size_t)bz * CIN * HW;

    float acc[2][4][4];
    #pragma unroll
    for (int mt = 0; mt < 2; mt++) {
        #pragma unroll
        for (int nt = 0; nt < 4; nt++) {
            #pragma unroll
            for (int q = 0; q < 4; q++) {
                acc[mt][nt][q] = 0.f;
            }
        }
    }

    for (int k0 = 0; k0 < CIN; k0 += 32) {
        #pragma unroll
        for (int i = 0; i < 8; i++) {
            int e = t + i * 256;
            int r = e >> 5;
            int c = e & 31;
            int gi = (cob + r) * CIN + k0 + c;
            Ah[r][c] = g_w1h[gi];
            Al[r][c] = g_w1l[gi];
        }
        #pragma unroll
        for (int i = 0; i < 16; i++) {
            int e = t + i * 256;
            int kk = e >> 7;
            int j = e & 127;
            int ci = k0 + kk;
            float v = fmaxf(fmaf(g_a1[ci], xb[ci * HW + p0 + j], g_b1[ci]), 0.f);
            splitf(v, &Bh[kk][j], &Bl[kk][j]);
        }
        __syncthreads();
        #pragma unroll
        for (int ks = 0; ks < 2; ks++) {
            const int kb = ks * 16;
            unsigned ah[2][4];
            unsigned al[2][4];
            unsigned bh[4][2];
            unsigned bl[4][2];
            #pragma unroll
            for (int mt = 0; mt < 2; mt++) {
                load_a_frag(ah[mt], &Ah[0][0], WPIT, m0 + mt * 16, kb, lane);
                load_a_frag(al[mt], &Al[0][0], WPIT, m0 + mt * 16, kb, lane);
            }
            #pragma unroll
            for (int hf = 0; hf < 2; hf++) {
                load_b_frag(bh[hf * 2], bh[hf * 2 + 1], &Bh[0][0], BPIT128, kb, n0 + hf * 16, lane);
                load_b_frag(bl[hf * 2], bl[hf * 2 + 1], &Bl[0][0], BPIT128, kb, n0 + hf * 16, lane);
            }
            #pragma unroll
            for (int mt = 0; mt < 2; mt++) {
                #pragma unroll
                for (int nt = 0; nt < 4; nt++) {
                    mma16816(acc[mt][nt], ah[mt], bh[nt]);
                    mma16816(acc[mt][nt], ah[mt], bl[nt]);
                    mma16816(acc[mt][nt], al[mt], bh[nt]);
                }
            }
        }
        __syncthreads();
    }
    #pragma unroll
    for (int mt = 0; mt < 2; mt++) {
        int co = cob + m0 + mt * 16 + (lane >> 2);
        float bv0 = bias[co];
        float bv8 = bias[co + 8];
        #pragma unroll
        for (int nt = 0; nt < 4; nt++) {
            int p = p0 + n0 + nt * 8 + 2 * (lane & 3);
            float2 v0;
            v0.x = acc[mt][nt][0] + bv0;
            v0.y = acc[mt][nt][1] + bv0;
            float2 v1;
            v1.x = acc[mt][nt][2] + bv8;
            v1.y = acc[mt][nt][3] + bv8;
            *(float2*)&g_f1[(bz * C1 + co) * HW + p] = v0;
            *(float2*)&g_f1[(bz * C1 + co + 8) * HW + p] = v1;
        }
    }
}

// ---------------- BN2 apply + zero pad ----------------
__global__ void pad_bn2_kernel() {
    int i = blockIdx.x * blockDim.x + threadIdx.x;
    if (i >= BATCH * C1 * HPWP) {
        return;
    }
    int pp = i % HPWP;
    int bc = i / HPWP;
    int c = bc % C1;
    int y = pp / HP;
    int xx = pp % HP;
    float v = 0.f;
    if (y >= 1 && y <= H && xx >= 1 && xx <= W) {
        v = fmaf(g_a2[c], g_f1[bc * HW + (y - 1) * W + (xx - 1)], g_b2[c]);
    }
    g_f2[i] = v;
}

// ---------------- offset/mod/dil conv: 32(co) x 128(px) ----------------
__global__ __launch_bounds__(256) void offconv_kernel() {
    __shared__ __nv_bfloat16 Ah[32][WPIT];
    __shared__ __nv_bfloat16 Al[32][WPIT];
    __shared__ __nv_bfloat16 Bh[32][BPIT128];
    __shared__ __nv_bfloat16 Bl[32][BPIT128];
    const int bz = blockIdx.z;
    const int p0 = blockIdx.x * 128;
    const int t = threadIdx.x;
    const int lane = t & 31;
    const int wid = t >> 5;
    const int n0 = wid * 16;
    const float* __restrict__ f2b = g_f2 + (size_t)bz * C1 * HPWP;

    float acc[2][2][4];
    #pragma unroll
    for (int mt = 0; mt < 2; mt++) {
        #pragma unroll
        for (int nt = 0; nt < 2; nt++) {
            #pragma unroll
            for (int q = 0; q < 4; q++) {
                acc[mt][nt][q] = 0.f;
            }
        }
    }

    for (int cc = 0; cc < 72; cc++) {
        const int tap = cc >> 3;
        const int ci0 = (cc & 7) * 32;
        const int dr = tap / 3;
        const int dc = tap % 3;
        const int kg = tap * C1 + ci0;
        #pragma unroll
        for (int i = 0; i < 4; i++) {
            int e = t + i * 256;
            int r = e >> 5;
            int c = e & 31;
            Ah[r][c] = g_w6h[r * KTOT + kg + c];
            Al[r][c] = g_w6l[r * KTOT + kg + c];
        }
        #pragma unroll
        for (int i = 0; i < 16; i++) {
            int e = t + i * 256;
            int kk = e >> 7;
            int j = e & 127;
            int p = p0 + j;
            int py = p / W;
            int px = p % W;
            float v = f2b[(ci0 + kk) * HPWP + (py + dr) * HP + (px + dc)];
            splitf(v, &Bh[kk][j], &Bl[kk][j]);
        }
        __syncthreads();
        #pragma unroll
        for (int ks = 0; ks < 2; ks++) {
            const int kb = ks * 16;
            unsigned ah[2][4];
            unsigned al[2][4];
            unsigned bh[2][2];
            unsigned bl[2][2];
            #pragma unroll
            for (int mt = 0; mt < 2; mt++) {
                load_a_frag(ah[mt], &Ah[0][0], WPIT, mt * 16, kb, lane);
                load_a_frag(al[mt], &Al[0][0], WPIT, mt * 16, kb, lane);
            }
            load_b_frag(bh[0], bh[1], &Bh[0][0], BPIT128, kb, n0, lane);
            load_b_frag(bl[0], bl[1], &Bl[0][0], BPIT128, kb, n0, lane);
            #pragma unroll
            for (int mt = 0; mt < 2; mt++) {
                #pragma unroll
                for (int nt = 0; nt < 2; nt++) {
                    mma16816(acc[mt][nt], ah[mt], bh[nt]);
                    mma16816(acc[mt][nt], ah[mt], bl[nt]);
                    mma16816(acc[mt][nt], al[mt], bh[nt]);
                }
            }
        }
        __syncthreads();
    }
    #pragma unroll
    for (int mt = 0; mt < 2; mt++) {
        #pragma unroll
        for (int hf = 0; hf < 2; hf++) {
            int co = mt * 16 + hf * 8 + (lane >> 2);
            if (co < COFF) {
                float bv = g_biasC[co];
                #pragma unroll
                for (int nt = 0; nt < 2; nt++) {
                    int p = p0 + n0 + nt * 8 + 2 * (lane & 3);
                    #pragma unroll
                    for (int q = 0; q < 2; q++) {
                        float v = acc[mt][nt][hf * 2 + q] + bv;
                        if (co >= 18 && co < 27) {
                            v = 1.f / (1.f + expf(-v));
                        } else if (co == 27) {
                            v = 2.f / (1.f + expf(-v));
                        }
                        g_off[(bz * COFF + co) * HW + p + q] = v;
                    }
                }
            }
        }
    }
}

// ---------------- deform: 64(o) x 64(px), gather + tensor-core --------------
__global__ __launch_bounds__(256) void deform_kernel(float* __restrict__ out) {
    __shared__ __nv_bfloat16 Ah[64][WPIT];
    __shared__ __nv_bfloat16 Al[64][WPIT];
    __shared__ __nv_bfloat16 Bh[32][BPIT64];
    __shared__ __nv_bfloat16 Bl[32][BPIT64];
    __shared__ float gwS[576][4];
    __shared__ int giS[576][4];
    const int bz = blockIdx.z;
    const int p0 = blockIdx.x * 64;
    const int t = threadIdx.x;
    const int lane = t & 31;
    const int wid = t >> 5;
    const int m0 = (wid >> 2) * 32;
    const int n0 = (wid & 3) * 16;
    const float* __restrict__ offb = g_off + (size_t)bz * COFF * HW;
    const float* __restrict__ f2b = g_f2 + (size_t)bz * C1 * HPWP;

    for (int e = t; e < 576; e += 256) {
        int j = e / NS;
        int n = e % NS;
        int p = p0 + j;
        int row = p / W;
        int col = p % W;
        float s = offb[27 * HW + p];
        float m = offb[(18 + n) * HW + p];
        float ox = offb[n * HW + p];
        float oy = offb[(9 + n) * HW + p];
        float fpx = (float)(row + 1) + 6.f * s * (float)(n / 3 - 1) + ox;
        float fpy = (float)(col + 1) + 6.f * s * (float)(n % 3 - 1) + oy;
        float fx = floorf(fpx);
        float fy = floorf(fpy);
        float qxl = fminf(fmaxf(fx, 0.f), 97.f);
        float qxr = fminf(fmaxf(fx + 1.f, 0.f), 97.f);
        float qyl = fminf(fmaxf(fy, 0.f), 97.f);
        float qyr = fminf(fmaxf(fy + 1.f, 0.f), 97.f);
        float pxc = fminf(fmaxf(fpx, 0.f), 97.f);
        float pyc = fminf(fmaxf(fpy, 0.f), 97.f);
        float wxl = 1.f + (qxl - pxc);
        float wxr = 1.f - (qxr - pxc);
        float wyl = 1.f + (qyl - pyc);
        float wyr = 1.f - (qyr - pyc);
        gwS[e][0] = wxl * wyl * m;
        gwS[e][1] = wxr * wyr * m;
        gwS[e][2] = wxl * wyr * m;
        gwS[e][3] = wxr * wyl * m;
        int ixl = (int)qxl * HP;
        int ixr = (int)qxr * HP;
        int iyl = (int)qyl;
        int iyr = (int)qyr;
        giS[e][0] = ixl + iyl;
        giS[e][1] = ixr + iyr;
        giS[e][2] = ixl + iyr;
        giS[e][3] = ixr + iyl;
    }
    __syncthreads();

    float acc[2][2][4];
    #pragma unroll
    for (int mt = 0; mt < 2; mt++) {
        #pragma unroll
        for (int nt = 0; nt < 2; nt++) {
            #pragma unroll
            for (int q = 0; q < 4; q++) {
                acc[mt][nt][q] = 0.f;
            }
        }
    }

    for (int cc = 0; cc < 72; cc++) {
        const int n = cc >> 3;
        const int ci0 = (cc & 7) * 32;
        const int kg = n * C1 + ci0;
        #pragma unroll
        for (int i = 0; i < 8; i++) {
            int e = t + i * 256;
            int r = e >> 5;
            int c = e & 31;
            Ah[r][c] = g_w7h[r * KTOT + kg + c];
            Al[r][c] = g_w7l[r * KTOT + kg + c];
        }
        #pragma unroll
        for (int i = 0; i < 8; i++) {
            int e = t + i * 256;
            int kk = e >> 6;
            int j = e & 63;
            const float* pl = f2b + (ci0 + kk) * HPWP;
            int g = j * NS + n;
            float4 w4 = *(const float4*)gwS[g];
            int4 i4 = *(const int4*)giS[g];
            float v = w4.x * pl[i4.x] + w4.y * pl[i4.y]
                    + w4.z * pl[i4.z] + w4.w * pl[i4.w];
            splitf(v, &Bh[kk][j], &Bl[kk][j]);
        }
        __syncthreads();
        #pragma unroll
        for (int ks = 0; ks < 2; ks++) {
            const int kb = ks * 16;
            unsigned ah[2][4];
            unsigned al[2][4];
            unsigned bh[2][2];
            unsigned bl[2][2];
            #pragma unroll
            for (int mt = 0; mt < 2; mt++) {
                load_a_frag(ah[mt], &Ah[0][0], WPIT, m0 + mt * 16, kb, lane);
                load_a_frag(al[mt], &Al[0][0], WPIT, m0 + mt * 16, kb, lane);
            }
            load_b_frag(bh[0], bh[1], &Bh[0][0], BPIT64, kb, n0, lane);
            load_b_frag(bl[0], bl[1], &Bl[0][0], BPIT64, kb, n0, lane);
            #pragma unroll
            for (int mt = 0; mt < 2; mt++) {
                #pragma unroll
                for (int nt = 0; nt < 2; nt++) {
                    mma16816(acc[mt][nt], ah[mt], bh[nt]);
                    mma16816(acc[mt][nt], ah[mt], bl[nt]);
                    mma16816(acc[mt][nt], al[mt], bh[nt]);
                }
            }
        }
        __syncthreads();
    }
    #pragma unroll
    for (int mt = 0; mt < 2; mt++) {
        int o = m0 + mt * 16 + (lane >> 2);
        #pragma unroll
        for (int nt = 0; nt < 2; nt++) {
            int p = p0 + n0 + nt * 8 + 2 * (lane & 3);
            float2 v0;
            v0.x = acc[mt][nt][0];
            v0.y = acc[mt][nt][1];
            float2 v1;
            v1.x = acc[mt][nt][2];
            v1.y = acc[mt][nt][3];
            *(float2*)&out[(bz * C2 + o) * HW + p] = v0;
            *(float2*)&out[(bz * C2 + o + 8) * HW + p] = v1;
        }
    }
}

// ---------------- launch ----------------
extern "C" void kernel_launch(void* const* d_in, const int* in_sizes, int n_in,
                              void* d_out, int out_size) {
    const float* x = (const float*)d_in[0];
    const float* bn1_g = (const float*)d_in[1];
    const float* bn1_b = (const float*)d_in[2];
    const float* w1 = (const float*)d_in[3];
    const float* b1 = (const float*)d_in[4];
    const float* bn2_g = (const float*)d_in[5];
    const float* bn2_b = (const float*)d_in[6];
    const float* pw = (const float*)d_in[7];
    const float* pb = (const float*)d_in[8];
    const float* mw = (const float*)d_in[9];
    const float* mb = (const float*)d_in[10];
    const float* dw = (const float*)d_in[11];
    const float* db = (const float*)d_in[12];
    const float* w7 = (const float*)d_in[13];
    float* out = (float*)d_out;

    prep_kernel<<<(C2 * KTOT + 255) / 256, 256>>>(w1, pw, pb, mw, mb, dw, db, w7);
    bn1_stats_kernel<<<CIN, 256>>>(x, bn1_g, bn1_b);
    conv1_kernel<<<dim3(HW / 128, C1 / 64, BATCH), 256>>>(x, b1);
    bn2_stats_kernel<<<C1, 256>>>(bn2_g, bn2_b);
    pad_bn2_kernel<<<(BATCH * C1 * HPWP + 255) / 256, 256>>>();
    offconv_kernel<<<dim3(HW / 128, 1, BATCH), 256>>>();
    deform_kernel<<<dim3(HW / 64, 1, BATCH), 256>>>(out);
}

// round 4
// speedup vs baseline: 1.5728x; 1.2342x over previous
#include <cuda_runtime.h>
#include <cuda_bf16.h>
#include <math.h>

#define H   96
#define W   96
#define HW  9216
#define HP  98
#define HPWP 9604
#define CIN 512
#define C1  256
#define C2  64
#define BATCH 2
#define NS  9
#define COFF 28
#define KTOT (C1*NS)
#define EPSV 1e-5f

#define WPIT 40
#define BPIT128 136
#define BPIT64  72

// ---------------- scratch ----------------
__device__ float g_f1[BATCH * C1 * HW];
__device__ float g_f2[BATCH * C1 * HPWP];      // float, for deform gather
__device__ unsigned g_f2p[BATCH * C1 * HPWP];  // packed bf16 hi|lo
__device__ unsigned g_xp[BATCH * CIN * HW];    // packed BN1+ReLU(x)
__device__ float g_off[BATCH * COFF * HW];
__device__ float g_a1[CIN];
__device__ float g_b1[CIN];
__device__ float g_a2[C1];
__device__ float g_b2[C1];
__device__ float g_biasC[32];
__device__ unsigned g_w1p[C1 * CIN];
__device__ unsigned g_w6p[32 * KTOT];
__device__ unsigned g_w7p[C2 * KTOT];

// ---------------- helpers ----------------
__device__ __forceinline__ unsigned packsplit(float v) {
    __nv_bfloat16 h = __float2bfloat16(v);
    float hf = __bfloat162float(h);
    __nv_bfloat16 l = __float2bfloat16(v - hf);
    return (unsigned)__bfloat16_as_ushort(h) | ((unsigned)__bfloat16_as_ushort(l) << 16);
}

__device__ __forceinline__ unsigned smaddr(const void* p) {
    return (unsigned)__cvta_generic_to_shared(p);
}

__device__ __forceinline__ void ldsm4(unsigned* r, unsigned a) {
    asm volatile("ldmatrix.sync.aligned.m8n8.x4.shared.b16 {%0,%1,%2,%3}, [%4];"
                 : "=r"(r[0]), "=r"(r[1]), "=r"(r[2]), "=r"(r[3])
                 : "r"(a));
}

__device__ __forceinline__ void ldsm4t(unsigned* r, unsigned a) {
    asm volatile("ldmatrix.sync.aligned.m8n8.x4.trans.shared.b16 {%0,%1,%2,%3}, [%4];"
                 : "=r"(r[0]), "=r"(r[1]), "=r"(r[2]), "=r"(r[3])
                 : "r"(a));
}

__device__ __forceinline__ void mma16816(float* c, const unsigned* a, const unsigned* b) {
    asm volatile("mma.sync.aligned.m16n8k16.row.col.f32.bf16.bf16.f32 "
                 "{%0,%1,%2,%3}, {%4,%5,%6,%7}, {%8,%9}, {%0,%1,%2,%3};"
                 : "+f"(c[0]), "+f"(c[1]), "+f"(c[2]), "+f"(c[3])
                 : "r"(a[0]), "r"(a[1]), "r"(a[2]), "r"(a[3]), "r"(b[0]), "r"(b[1]));
}

__device__ __forceinline__ void load_a_frag(unsigned* a, const unsigned short* base,
                                            int pitch, int row0, int kb, int lane) {
    const unsigned short* p = base + (row0 + (lane & 15)) * pitch + kb + ((lane >> 4) * 8);
    ldsm4(a, smaddr(p));
}

__device__ __forceinline__ void load_b_frag(unsigned b0[2], unsigned b1[2],
                                            const unsigned short* base,
                                            int pitch, int kb, int n0, int lane) {
    unsigned tmp[4];
    const unsigned short* p = base + (kb + (lane & 15)) * pitch + n0 + ((lane >> 4) * 8);
    ldsm4t(tmp, smaddr(p));
    b0[0] = tmp[0];
    b0[1] = tmp[1];
    b1[0] = tmp[2];
    b1[1] = tmp[3];
}

// ---------------- weight prep ----------------
__global__ void prep_kernel(const float* __restrict__ w1,
                            const float* __restrict__ pw, const float* __restrict__ pb,
                            const float* __restrict__ mw, const float* __restrict__ mb,
                            const float* __restrict__ dw, const float* __restrict__ db,
                            const float* __restrict__ w7) {
    int i = blockIdx.x * blockDim.x + threadIdx.x;
    if (i < C1 * CIN) {
        g_w1p[i] = packsplit(w1[i]);
    }
    if (i < 32 * KTOT) {
        int co = i / KTOT;
        int k = i % KTOT;
        int r = k / C1;
        int ci = k % C1;
        float v = 0.f;
        if (co < 18) {
            v = pw[(co * C1 + ci) * NS + r];
        } else if (co < 27) {
            v = mw[((co - 18) * C1 + ci) * NS + r];
        } else if (co == 27) {
            v = dw[ci * NS + r];
        }
        g_w6p[i] = packsplit(v);
    }
    if (i < C2 * KTOT) {
        int o = i / KTOT;
        int k = i % KTOT;
        int n = k / C1;
        int ci = k % C1;
        g_w7p[i] = packsplit(w7[(o * C1 + ci) * NS + n]);
    }
    if (i < 32) {
        float v = 0.f;
        if (i < 18) {
            v = pb[i];
        } else if (i < 27) {
            v = mb[i - 18];
        } else if (i == 27) {
            v = db[0];
        }
        g_biasC[i] = v;
    }
}

// ---------------- BN stats ----------------
__device__ __forceinline__ void bn_reduce(float s, float s2, float* sh,
                                          float gamma, float beta,
                                          float* a_out, float* b_out, int c) {
    sh[threadIdx.x] = s;
    sh[256 + threadIdx.x] = s2;
    __syncthreads();
    for (int st = 128; st > 0; st >>= 1) {
        if (threadIdx.x < st) {
            sh[threadIdx.x] += sh[threadIdx.x + st];
            sh[256 + threadIdx.x] += sh[256 + threadIdx.x + st];
        }
        __syncthreads();
    }
    if (threadIdx.x == 0) {
        const float inv = 1.f / (float)(BATCH * HW);
        float mean = sh[0] * inv;
        float var = sh[256] * inv - mean * mean;
        float a = gamma / sqrtf(var + EPSV);
        a_out[c] = a;
        b_out[c] = beta - mean * a;
    }
}

__global__ void bn1_stats_kernel(const float* __restrict__ x,
                                 const float* __restrict__ gamma,
                                 const float* __restrict__ beta) {
    __shared__ float sh[512];
    int c = blockIdx.x;
    float s = 0.f;
    float s2 = 0.f;
    #pragma unroll
    for (int bb = 0; bb < BATCH; bb++) {
        const float4* pl = (const float4*)(x + ((size_t)bb * CIN + c) * HW);
        for (int q = threadIdx.x; q < HW / 4; q += 256) {
            float4 v = pl[q];
            s += v.x + v.y + v.z + v.w;
            s2 += v.x * v.x + v.y * v.y + v.z * v.z + v.w * v.w;
        }
    }
    bn_reduce(s, s2, sh, gamma[c], beta[c], g_a1, g_b1, c);
}

__global__ void bn2_stats_kernel(const float* __restrict__ gamma,
                                 const float* __restrict__ beta) {
    __shared__ float sh[512];
    int c = blockIdx.x;
    float s = 0.f;
    float s2 = 0.f;
    #pragma unroll
    for (int bb = 0; bb < BATCH; bb++) {
        const float4* pl = (const float4*)(g_f1 + ((size_t)bb * C1 + c) * HW);
        for (int q = threadIdx.x; q < HW / 4; q += 256) {
            float4 v = pl[q];
            s += v.x + v.y + v.z + v.w;
            s2 += v.x * v.x + v.y * v.y + v.z * v.z + v.w * v.w;
        }
    }
    bn_reduce(s, s2, sh, gamma[c], beta[c], g_a2, g_b2, c);
}

// ---------------- xcvt: BN1+ReLU+split pack of x (once) ----------------
__global__ void xcvt_kernel(const float* __restrict__ x) {
    int i4 = blockIdx.x * blockDim.x + threadIdx.x;
    if (i4 >= BATCH * CIN * HW / 4) {
        return;
    }
    int c = (i4 * 4 / HW) % CIN;
    float a = g_a1[c];
    float b = g_b1[c];
    float4 v = ((const float4*)x)[i4];
    uint4 o;
    o.x = packsplit(fmaxf(fmaf(a, v.x, b), 0.f));
    o.y = packsplit(fmaxf(fmaf(a, v.y, b), 0.f));
    o.z = packsplit(fmaxf(fmaf(a, v.z, b), 0.f));
    o.w = packsplit(fmaxf(fmaf(a, v.w, b), 0.f));
    ((uint4*)g_xp)[i4] = o;
}

// ---------------- conv1: 64(co) x 128(px), tensor-core ----------------
__global__ __launch_bounds__(256) void conv1_kernel(const float* __restrict__ bias) {
    __shared__ unsigned short Ah[64][WPIT];
    __shared__ unsigned short Al[64][WPIT];
    __shared__ unsigned short Bh[32][BPIT128];
    __shared__ unsigned short Bl[32][BPIT128];
    const int bz = blockIdx.z;
    const int p0 = blockIdx.x * 128;
    const int cob = blockIdx.y * 64;
    const int t = threadIdx.x;
    const int lane = t & 31;
    const int wid = t >> 5;
    const int m0 = (wid >> 2) * 32;
    const int n0 = (wid & 3) * 32;
    const unsigned* __restrict__ xpb = g_xp + (size_t)bz * CIN * HW;

    // loop-invariant fill coordinates
    const int ac2 = t & 15;          // A pair-col
    const int ar0 = t >> 4;          // A row base (step 16)
    const int bj2 = t & 63;          // B pair-col
    const int bk0 = t >> 6;          // B row base (step 4)

    float acc[2][4][4];
    #pragma unroll
    for (int mt = 0; mt < 2; mt++) {
        #pragma unroll
        for (int nt = 0; nt < 4; nt++) {
            #pragma unroll
            for (int q = 0; q < 4; q++) {
                acc[mt][nt][q] = 0.f;
            }
        }
    }

    for (int k0 = 0; k0 < CIN; k0 += 32) {
        #pragma unroll
        for (int i = 0; i < 4; i++) {
            int r = ar0 + 16 * i;
            uint2 wv = *(const uint2*)&g_w1p[(cob + r) * CIN + k0 + ac2 * 2];
            *(unsigned*)&Ah[r][ac2 * 2] = __byte_perm(wv.x, wv.y, 0x5410);
            *(unsigned*)&Al[r][ac2 * 2] = __byte_perm(wv.x, wv.y, 0x7632);
        }
        #pragma unroll
        for (int i = 0; i < 8; i++) {
            int kk = bk0 + 4 * i;
            uint2 xv = *(const uint2*)&xpb[(k0 + kk) * HW + p0 + bj2 * 2];
            *(unsigned*)&Bh[kk][bj2 * 2] = __byte_perm(xv.x, xv.y, 0x5410);
            *(unsigned*)&Bl[kk][bj2 * 2] = __byte_perm(xv.x, xv.y, 0x7632);
        }
        __syncthreads();
        #pragma unroll
        for (int ks = 0; ks < 2; ks++) {
            const int kb = ks * 16;
            unsigned ah[2][4];
            unsigned al[2][4];
            unsigned bh[4][2];
            unsigned bl[4][2];
            #pragma unroll
            for (int mt = 0; mt < 2; mt++) {
                load_a_frag(ah[mt], &Ah[0][0], WPIT, m0 + mt * 16, kb, lane);
                load_a_frag(al[mt], &Al[0][0], WPIT, m0 + mt * 16, kb, lane);
            }
            #pragma unroll
            for (int hf = 0; hf < 2; hf++) {
                load_b_frag(bh[hf * 2], bh[hf * 2 + 1], &Bh[0][0], BPIT128, kb, n0 + hf * 16, lane);
                load_b_frag(bl[hf * 2], bl[hf * 2 + 1], &Bl[0][0], BPIT128, kb, n0 + hf * 16, lane);
            }
            #pragma unroll
            for (int mt = 0; mt < 2; mt++) {
                #pragma unroll
                for (int nt = 0; nt < 4; nt++) {
                    mma16816(acc[mt][nt], ah[mt], bh[nt]);
                    mma16816(acc[mt][nt], ah[mt], bl[nt]);
                    mma16816(acc[mt][nt], al[mt], bh[nt]);
                }
            }
        }
        __syncthreads();
    }
    #pragma unroll
    for (int mt = 0; mt < 2; mt++) {
        int co = cob + m0 + mt * 16 + (lane >> 2);
        float bv0 = bias[co];
        float bv8 = bias[co + 8];
        #pragma unroll
        for (int nt = 0; nt < 4; nt++) {
            int p = p0 + n0 + nt * 8 + 2 * (lane & 3);
            float2 v0;
            v0.x = acc[mt][nt][0] + bv0;
            v0.y = acc[mt][nt][1] + bv0;
            float2 v1;
            v1.x = acc[mt][nt][2] + bv8;
            v1.y = acc[mt][nt][3] + bv8;
            *(float2*)&g_f1[(bz * C1 + co) * HW + p] = v0;
            *(float2*)&g_f1[(bz * C1 + co + 8) * HW + p] = v1;
        }
    }
}

// ---------------- BN2 apply + zero pad (float + packed) ----------------
__global__ void pad_bn2_kernel() {
    int i = blockIdx.x * blockDim.x + threadIdx.x;
    if (i >= BATCH * C1 * HPWP) {
        return;
    }
    int pp = i % HPWP;
    int bc = i / HPWP;
    int c = bc % C1;
    int y = pp / HP;
    int xx = pp % HP;
    float v = 0.f;
    if (y >= 1 && y <= H && xx >= 1 && xx <= W) {
        v = fmaf(g_a2[c], g_f1[bc * HW + (y - 1) * W + (xx - 1)], g_b2[c]);
    }
    g_f2[i] = v;
    g_f2p[i] = packsplit(v);
}

// ---------------- offset/mod/dil conv: 32(co) x 128(px) ----------------
__global__ __launch_bounds__(256) void offconv_kernel() {
    __shared__ unsigned short Ah[32][WPIT];
    __shared__ unsigned short Al[32][WPIT];
    __shared__ unsigned short Bh[32][BPIT128];
    __shared__ unsigned short Bl[32][BPIT128];
    const int bz = blockIdx.z;
    const int p0 = blockIdx.x * 128;
    const int t = threadIdx.x;
    const int lane = t & 31;
    const int wid = t >> 5;
    const int n0 = wid * 16;
    const unsigned* __restrict__ f2pb = g_f2p + (size_t)bz * C1 * HPWP;

    // loop-invariant fill coordinates
    const int ac2 = t & 15;
    const int ar0 = t >> 4;          // step 16, 2 iters
    const int bj = t & 127;          // B col
    const int bk0 = t >> 7;          // step 2, 16 iters
    const int bpy = (p0 + bj) / W;
    const int bpx = (p0 + bj) % W;
    const int boff = bpy * HP + bpx;

    float acc[2][2][4];
    #pragma unroll
    for (int mt = 0; mt < 2; mt++) {
        #pragma unroll
        for (int nt = 0; nt < 2; nt++) {
            #pragma unroll
            for (int q = 0; q < 4; q++) {
                acc[mt][nt][q] = 0.f;
            }
        }
    }

    for (int cc = 0; cc < 72; cc++) {
        const int tap = cc >> 3;
        const int ci0 = (cc & 7) * 32;
        const int dr = tap / 3;
        const int dc = tap % 3;
        const int kg = tap * C1 + ci0;
        #pragma unroll
        for (int i = 0; i < 2; i++) {
            int r = ar0 + 16 * i;
            uint2 wv = *(const uint2*)&g_w6p[r * KTOT + kg + ac2 * 2];
            *(unsigned*)&Ah[r][ac2 * 2] = __byte_perm(wv.x, wv.y, 0x5410);
            *(unsigned*)&Al[r][ac2 * 2] = __byte_perm(wv.x, wv.y, 0x7632);
        }
        {
            const unsigned* src = f2pb + boff + dr * HP + dc;
            #pragma unroll
            for (int i = 0; i < 16; i++) {
                int kk = bk0 + 2 * i;
                unsigned w = src[(ci0 + kk) * HPWP];
                Bh[kk][bj] = (unsigned short)(w & 0xffffu);
                Bl[kk][bj] = (unsigned short)(w >> 16);
            }
        }
        __syncthreads();
        #pragma unroll
        for (int ks = 0; ks < 2; ks++) {
            const int kb = ks * 16;
            unsigned ah[2][4];
            unsigned al[2][4];
            unsigned bh[2][2];
            unsigned bl[2][2];
            #pragma unroll
            for (int mt = 0; mt < 2; mt++) {
                load_a_frag(ah[mt], &Ah[0][0], WPIT, mt * 16, kb, lane);
                load_a_frag(al[mt], &Al[0][0], WPIT, mt * 16, kb, lane);
            }
            load_b_frag(bh[0], bh[1], &Bh[0][0], BPIT128, kb, n0, lane);
            load_b_frag(bl[0], bl[1], &Bl[0][0], BPIT128, kb, n0, lane);
            #pragma unroll
            for (int mt = 0; mt < 2; mt++) {
                #pragma unroll
                for (int nt = 0; nt < 2; nt++) {
                    mma16816(acc[mt][nt], ah[mt], bh[nt]);
                    mma16816(acc[mt][nt], ah[mt], bl[nt]);
                    mma16816(acc[mt][nt], al[mt], bh[nt]);
                }
            }
        }
        __syncthreads();
    }
    #pragma unroll
    for (int mt = 0; mt < 2; mt++) {
        #pragma unroll
        for (int hf = 0; hf < 2; hf++) {
            int co = mt * 16 + hf * 8 + (lane >> 2);
            if (co < COFF) {
                float bv = g_biasC[co];
                #pragma unroll
                for (int nt = 0; nt < 2; nt++) {
                    int p = p0 + n0 + nt * 8 + 2 * (lane & 3);
                    #pragma unroll
                    for (int q = 0; q < 2; q++) {
                        float v = acc[mt][nt][hf * 2 + q] + bv;
                        if (co >= 18 && co < 27) {
                            v = 1.f / (1.f + expf(-v));
                        } else if (co == 27) {
                            v = 2.f / (1.f + expf(-v));
                        }
                        g_off[(bz * COFF + co) * HW + p + q] = v;
                    }
                }
            }
        }
    }
}

// ---------------- deform: 64(o) x 64(px), gather + tensor-core --------------
__global__ __launch_bounds__(256) void deform_kernel(float* __restrict__ out) {
    __shared__ unsigned short Ah[64][WPIT];
    __shared__ unsigned short Al[64][WPIT];
    __shared__ unsigned short Bh[32][BPIT64];
    __shared__ unsigned short Bl[32][BPIT64];
    __shared__ float gwS[576][4];
    __shared__ int giS[576][4];
    const int bz = blockIdx.z;
    const int p0 = blockIdx.x * 64;
    const int t = threadIdx.x;
    const int lane = t & 31;
    const int wid = t >> 5;
    const int m0 = (wid >> 2) * 32;
    const int n0 = (wid & 3) * 16;
    const float* __restrict__ offb = g_off + (size_t)bz * COFF * HW;
    const float* __restrict__ f2b = g_f2 + (size_t)bz * C1 * HPWP;

    for (int e = t; e < 576; e += 256) {
        int j = e / NS;
        int n = e % NS;
        int p = p0 + j;
        int row = p / W;
        int col = p % W;
        float s = offb[27 * HW + p];
        float m = offb[(18 + n) * HW + p];
        float ox = offb[n * HW + p];
        float oy = offb[(9 + n) * HW + p];
        float fpx = (float)(row + 1) + 6.f * s * (float)(n / 3 - 1) + ox;
        float fpy = (float)(col + 1) + 6.f * s * (float)(n % 3 - 1) + oy;
        float fx = floorf(fpx);
        float fy = floorf(fpy);
        float qxl = fminf(fmaxf(fx, 0.f), 97.f);
        float qxr = fminf(fmaxf(fx + 1.f, 0.f), 97.f);
        float qyl = fminf(fmaxf(fy, 0.f), 97.f);
        float qyr = fminf(fmaxf(fy + 1.f, 0.f), 97.f);
        float pxc = fminf(fmaxf(fpx, 0.f), 97.f);
        float pyc = fminf(fmaxf(fpy, 0.f), 97.f);
        float wxl = 1.f + (qxl - pxc);
        float wxr = 1.f - (qxr - pxc);
        float wyl = 1.f + (qyl - pyc);
        float wyr = 1.f - (qyr - pyc);
        gwS[e][0] = wxl * wyl * m;
        gwS[e][1] = wxr * wyr * m;
        gwS[e][2] = wxl * wyr * m;
        gwS[e][3] = wxr * wyl * m;
        int ixl = (int)qxl * HP;
        int ixr = (int)qxr * HP;
        int iyl = (int)qyl;
        int iyr = (int)qyr;
        giS[e][0] = ixl + iyl;
        giS[e][1] = ixr + iyr;
        giS[e][2] = ixl + iyr;
        giS[e][3] = ixr + iyl;
    }
    __syncthreads();

    // loop-invariant fill coordinates
    const int ac2 = t & 15;
    const int ar0 = t >> 4;          // step 16, 4 iters
    const int bj = t & 63;           // B col, fixed
    const int bk0 = t >> 6;          // step 4, 8 iters

    float acc[2][2][4];
    #pragma unroll
    for (int mt = 0; mt < 2; mt++) {
        #pragma unroll
        for (int nt = 0; nt < 2; nt++) {
            #pragma unroll
            for (int q = 0; q < 4; q++) {
                acc[mt][nt][q] = 0.f;
            }
        }
    }

    for (int cc = 0; cc < 72; cc++) {
        const int n = cc >> 3;
        const int ci0 = (cc & 7) * 32;
        const int kg = n * C1 + ci0;
        #pragma unroll
        for (int i = 0; i < 4; i++) {
            int r = ar0 + 16 * i;
            uint2 wv = *(const uint2*)&g_w7p[r * KTOT + kg + ac2 * 2];
            *(unsigned*)&Ah[r][ac2 * 2] = __byte_perm(wv.x, wv.y, 0x5410);
            *(unsigned*)&Al[r][ac2 * 2] = __byte_perm(wv.x, wv.y, 0x7632);
        }
        {
            int g = bj * NS + n;
            float4 w4 = *(const float4*)gwS[g];
            int4 i4 = *(const int4*)giS[g];
            const float* plb = f2b + ci0 * HPWP;
            #pragma unroll
            for (int i = 0; i < 8; i++) {
                int kk = bk0 + 4 * i;
                const float* pl = plb + kk * HPWP;
                float v = w4.x * pl[i4.x] + w4.y * pl[i4.y]
                        + w4.z * pl[i4.z] + w4.w * pl[i4.w];
                unsigned pv = packsplit(v);
                Bh[kk][bj] = (unsigned short)(pv & 0xffffu);
                Bl[kk][bj] = (unsigned short)(pv >> 16);
            }
        }
        __syncthreads();
        #pragma unroll
        for (int ks = 0; ks < 2; ks++) {
            const int kb = ks * 16;
            unsigned ah[2][4];
            unsigned al[2][4];
            unsigned bh[2][2];
            unsigned bl[2][2];
            #pragma unroll
            for (int mt = 0; mt < 2; mt++) {
                load_a_frag(ah[mt], &Ah[0][0], WPIT, m0 + mt * 16, kb, lane);
                load_a_frag(al[mt], &Al[0][0], WPIT, m0 + mt * 16, kb, lane);
            }
            load_b_frag(bh[0], bh[1], &Bh[0][0], BPIT64, kb, n0, lane);
            load_b_frag(bl[0], bl[1], &Bl[0][0], BPIT64, kb, n0, lane);
            #pragma unroll
            for (int mt = 0; mt < 2; mt++) {
                #pragma unroll
                for (int nt = 0; nt < 2; nt++) {
                    mma16816(acc[mt][nt], ah[mt], bh[nt]);
                    mma16816(acc[mt][nt], ah[mt], bl[nt]);
                    mma16816(acc[mt][nt], al[mt], bh[nt]);
                }
            }
        }
        __syncthreads();
    }
    #pragma unroll
    for (int mt = 0; mt < 2; mt++) {
        int o = m0 + mt * 16 + (lane >> 2);
        #pragma unroll
        for (int nt = 0; nt < 2; nt++) {
            int p = p0 + n0 + nt * 8 + 2 * (lane & 3);
            float2 v0;
            v0.x = acc[mt][nt][0];
            v0.y = acc[mt][nt][1];
            float2 v1;
            v1.x = acc[mt][nt][2];
            v1.y = acc[mt][nt][3];
            *(float2*)&out[(bz * C2 + o) * HW + p] = v0;
            *(float2*)&out[(bz * C2 + o + 8) * HW + p] = v1;
        }
    }
}

// ---------------- launch ----------------
extern "C" void kernel_launch(void* const* d_in, const int* in_sizes, int n_in,
                              void* d_out, int out_size) {
    const float* x = (const float*)d_in[0];
    const float* bn1_g = (const float*)d_in[1];
    const float* bn1_b = (const float*)d_in[2];
    const float* w1 = (const float*)d_in[3];
    const float* b1 = (const float*)d_in[4];
    const float* bn2_g = (const float*)d_in[5];
    const float* bn2_b = (const float*)d_in[6];
    const float* pw = (const float*)d_in[7];
    const float* pb = (const float*)d_in[8];
    const float* mw = (const float*)d_in[9];
    const float* mb = (const float*)d_in[10];
    const float* dw = (const float*)d_in[11];
    const float* db = (const float*)d_in[12];
    const float* w7 = (const float*)d_in[13];
    float* out = (float*)d_out;

    prep_kernel<<<(C2 * KTOT + 255) / 256, 256>>>(w1, pw, pb, mw, mb, dw, db, w7);
    bn1_stats_kernel<<<CIN, 256>>>(x, bn1_g, bn1_b);
    xcvt_kernel<<<(BATCH * CIN * HW / 4 + 255) / 256, 256>>>(x);
    conv1_kernel<<<dim3(HW / 128, C1 / 64, BATCH), 256>>>(b1);
    bn2_stats_kernel<<<C1, 256>>>(bn2_g, bn2_b);
    pad_bn2_kernel<<<(BATCH * C1 * HPWP + 255) / 256, 256>>>();
    offconv_kernel<<<dim3(HW / 128, 1, BATCH), 256>>>();
    deform_kernel<<<dim3(HW / 64, 1, BATCH), 256>>>(out);
}

// round 5
// speedup vs baseline: 1.9580x; 1.2449x over previous
#include <cuda_runtime.h>
#include <cuda_bf16.h>
#include <math.h>

#define H   96
#define W   96
#define HW  9216
#define HP  98
#define HPWP 9604
#define CIN 512
#define C1  256
#define C2  64
#define BATCH 2
#define NS  9
#define COFF 28
#define KTOT (C1*NS)
#define EPSV 1e-5f

#define WPIT 40
#define BPIT128 136
#define BPIT64  72

// ---------------- scratch ----------------
__device__ float g_f1[BATCH * C1 * HW];
__device__ float g_f2[BATCH * C1 * HPWP];      // float, for deform gather
__device__ unsigned g_f2p[BATCH * C1 * HPWP];  // packed bf16 hi|lo, for offconv
__device__ unsigned short g_xh[BATCH * CIN * HW];  // planar bf16 hi of BN1+ReLU(x)
__device__ unsigned short g_xl[BATCH * CIN * HW];  // planar bf16 lo
__device__ float g_off[BATCH * COFF * HW];
__device__ float g_a1[CIN];
__device__ float g_b1[CIN];
__device__ float g_a2[C1];
__device__ float g_b2[C1];
__device__ float g_biasC[32];
__device__ unsigned short g_w1h[C1 * CIN];
__device__ unsigned short g_w1l[C1 * CIN];
__device__ unsigned short g_w6h[32 * KTOT];
__device__ unsigned short g_w6l[32 * KTOT];
__device__ unsigned short g_w7h[C2 * KTOT];
__device__ unsigned short g_w7l[C2 * KTOT];

// ---------------- helpers ----------------
__device__ __forceinline__ unsigned packsplit(float v) {
    __nv_bfloat16 h = __float2bfloat16(v);
    float hf = __bfloat162float(h);
    __nv_bfloat16 l = __float2bfloat16(v - hf);
    return (unsigned)__bfloat16_as_ushort(h) | ((unsigned)__bfloat16_as_ushort(l) << 16);
}

__device__ __forceinline__ unsigned smaddr(const void* p) {
    return (unsigned)__cvta_generic_to_shared(p);
}

__device__ __forceinline__ void cpa16(void* dst, const void* src) {
    asm volatile("cp.async.cg.shared.global [%0], [%1], 16;"
                 :: "r"(smaddr(dst)), "l"(src));
}
__device__ __forceinline__ void cpa_commit() {
    asm volatile("cp.async.commit_group;");
}
__device__ __forceinline__ void cpa_wait0() {
    asm volatile("cp.async.wait_group 0;");
}
__device__ __forceinline__ void cpa_wait1() {
    asm volatile("cp.async.wait_group 1;");
}

__device__ __forceinline__ void ldsm4(unsigned* r, unsigned a) {
    asm volatile("ldmatrix.sync.aligned.m8n8.x4.shared.b16 {%0,%1,%2,%3}, [%4];"
                 : "=r"(r[0]), "=r"(r[1]), "=r"(r[2]), "=r"(r[3])
                 : "r"(a));
}

__device__ __forceinline__ void ldsm4t(unsigned* r, unsigned a) {
    asm volatile("ldmatrix.sync.aligned.m8n8.x4.trans.shared.b16 {%0,%1,%2,%3}, [%4];"
                 : "=r"(r[0]), "=r"(r[1]), "=r"(r[2]), "=r"(r[3])
                 : "r"(a));
}

__device__ __forceinline__ void mma16816(float* c, const unsigned* a, const unsigned* b) {
    asm volatile("mma.sync.aligned.m16n8k16.row.col.f32.bf16.bf16.f32 "
                 "{%0,%1,%2,%3}, {%4,%5,%6,%7}, {%8,%9}, {%0,%1,%2,%3};"
                 : "+f"(c[0]), "+f"(c[1]), "+f"(c[2]), "+f"(c[3])
                 : "r"(a[0]), "r"(a[1]), "r"(a[2]), "r"(a[3]), "r"(b[0]), "r"(b[1]));
}

__device__ __forceinline__ void load_a_frag(unsigned* a, const unsigned short* base,
                                            int pitch, int row0, int kb, int lane) {
    const unsigned short* p = base + (row0 + (lane & 15)) * pitch + kb + ((lane >> 4) * 8);
    ldsm4(a, smaddr(p));
}

__device__ __forceinline__ void load_b_frag(unsigned b0[2], unsigned b1[2],
                                            const unsigned short* base,
                                            int pitch, int kb, int n0, int lane) {
    unsigned tmp[4];
    const unsigned short* p = base + (kb + (lane & 15)) * pitch + n0 + ((lane >> 4) * 8);
    ldsm4t(tmp, smaddr(p));
    b0[0] = tmp[0];
    b0[1] = tmp[1];
    b1[0] = tmp[2];
    b1[1] = tmp[3];
}

// ---------------- weight prep ----------------
__global__ void prep_kernel(const float* __restrict__ w1,
                            const float* __restrict__ pw, const float* __restrict__ pb,
                            const float* __restrict__ mw, const float* __restrict__ mb,
                            const float* __restrict__ dw, const float* __restrict__ db,
                            const float* __restrict__ w7) {
    int i = blockIdx.x * blockDim.x + threadIdx.x;
    if (i < C1 * CIN) {
        unsigned p = packsplit(w1[i]);
        g_w1h[i] = (unsigned short)(p & 0xffffu);
        g_w1l[i] = (unsigned short)(p >> 16);
    }
    if (i < 32 * KTOT) {
        int co = i / KTOT;
        int k = i % KTOT;
        int r = k / C1;
        int ci = k % C1;
        float v = 0.f;
        if (co < 18) {
            v = pw[(co * C1 + ci) * NS + r];
        } else if (co < 27) {
            v = mw[((co - 18) * C1 + ci) * NS + r];
        } else if (co == 27) {
            v = dw[ci * NS + r];
        }
        unsigned p = packsplit(v);
        g_w6h[i] = (unsigned short)(p & 0xffffu);
        g_w6l[i] = (unsigned short)(p >> 16);
    }
    if (i < C2 * KTOT) {
        int o = i / KTOT;
        int k = i % KTOT;
        int n = k / C1;
        int ci = k % C1;
        unsigned p = packsplit(w7[(o * C1 + ci) * NS + n]);
        g_w7h[i] = (unsigned short)(p & 0xffffu);
        g_w7l[i] = (unsigned short)(p >> 16);
    }
    if (i < 32) {
        float v = 0.f;
        if (i < 18) {
            v = pb[i];
        } else if (i < 27) {
            v = mb[i - 18];
        } else if (i == 27) {
            v = db[0];
        }
        g_biasC[i] = v;
    }
}

// ---------------- BN stats ----------------
__device__ __forceinline__ void bn_reduce(float s, float s2, float* sh,
                                          float gamma, float beta,
                                          float* a_out, float* b_out, int c) {
    sh[threadIdx.x] = s;
    sh[256 + threadIdx.x] = s2;
    __syncthreads();
    for (int st = 128; st > 0; st >>= 1) {
        if (threadIdx.x < st) {
            sh[threadIdx.x] += sh[threadIdx.x + st];
            sh[256 + threadIdx.x] += sh[256 + threadIdx.x + st];
        }
        __syncthreads();
    }
    if (threadIdx.x == 0) {
        const float inv = 1.f / (float)(BATCH * HW);
        float mean = sh[0] * inv;
        float var = sh[256] * inv - mean * mean;
        float a = gamma / sqrtf(var + EPSV);
        a_out[c] = a;
        b_out[c] = beta - mean * a;
    }
}

__global__ void bn1_stats_kernel(const float* __restrict__ x,
                                 const float* __restrict__ gamma,
                                 const float* __restrict__ beta) {
    __shared__ float sh[512];
    int c = blockIdx.x;
    float s = 0.f;
    float s2 = 0.f;
    #pragma unroll
    for (int bb = 0; bb < BATCH; bb++) {
        const float4* pl = (const float4*)(x + ((size_t)bb * CIN + c) * HW);
        for (int q = threadIdx.x; q < HW / 4; q += 256) {
            float4 v = pl[q];
            s += v.x + v.y + v.z + v.w;
            s2 += v.x * v.x + v.y * v.y + v.z * v.z + v.w * v.w;
        }
    }
    bn_reduce(s, s2, sh, gamma[c], beta[c], g_a1, g_b1, c);
}

__global__ void bn2_stats_kernel(const float* __restrict__ gamma,
                                 const float* __restrict__ beta) {
    __shared__ float sh[512];
    int c = blockIdx.x;
    float s = 0.f;
    float s2 = 0.f;
    #pragma unroll
    for (int bb = 0; bb < BATCH; bb++) {
        const float4* pl = (const float4*)(g_f1 + ((size_t)bb * C1 + c) * HW);
        for (int q = threadIdx.x; q < HW / 4; q += 256) {
            float4 v = pl[q];
            s += v.x + v.y + v.z + v.w;
            s2 += v.x * v.x + v.y * v.y + v.z * v.z + v.w * v.w;
        }
    }
    bn_reduce(s, s2, sh, gamma[c], beta[c], g_a2, g_b2, c);
}

// ---------------- xcvt: BN1+ReLU+split pack of x ----------------
__global__ void xcvt_kernel(const float* __restrict__ x) {
    int i4 = blockIdx.x * blockDim.x + threadIdx.x;
    if (i4 >= BATCH * CIN * HW / 4) {
        return;
    }
    int c = (i4 * 4 / HW) % CIN;
    float a = g_a1[c];
    float b = g_b1[c];
    float4 v = ((const float4*)x)[i4];
    unsigned p0 = packsplit(fmaxf(fmaf(a, v.x, b), 0.f));
    unsigned p1 = packsplit(fmaxf(fmaf(a, v.y, b), 0.f));
    unsigned p2 = packsplit(fmaxf(fmaf(a, v.z, b), 0.f));
    unsigned p3 = packsplit(fmaxf(fmaf(a, v.w, b), 0.f));
    ushort4 oh;
    oh.x = (unsigned short)(p0 & 0xffffu);
    oh.y = (unsigned short)(p1 & 0xffffu);
    oh.z = (unsigned short)(p2 & 0xffffu);
    oh.w = (unsigned short)(p3 & 0xffffu);
    ushort4 ol;
    ol.x = (unsigned short)(p0 >> 16);
    ol.y = (unsigned short)(p1 >> 16);
    ol.z = (unsigned short)(p2 >> 16);
    ol.w = (unsigned short)(p3 >> 16);
    ((ushort4*)g_xh)[i4] = oh;
    ((ushort4*)g_xl)[i4] = ol;
}

// ---------------- conv1: 64(co) x 128(px), cp.async double-buffered ----------
__global__ __launch_bounds__(256) void conv1_kernel(const float* __restrict__ bias) {
    __shared__ unsigned short Ah[2][64][WPIT];
    __shared__ unsigned short Al[2][64][WPIT];
    __shared__ unsigned short Bh[2][32][BPIT128];
    __shared__ unsigned short Bl[2][32][BPIT128];
    const int bz = blockIdx.z;
    const int p0 = blockIdx.x * 128;
    const int cob = blockIdx.y * 64;
    const int t = threadIdx.x;
    const int lane = t & 31;
    const int wid = t >> 5;
    const int m0 = (wid >> 2) * 32;
    const int n0 = (wid & 3) * 32;
    const unsigned short* __restrict__ xh = g_xh + (size_t)bz * CIN * HW;
    const unsigned short* __restrict__ xl = g_xl + (size_t)bz * CIN * HW;

    // fill coords
    const int far_ = t >> 2;          // A row 0..63
    const int fac = (t & 3) * 8;      // A col8

    float acc[2][4][4];
    #pragma unroll
    for (int mt = 0; mt < 2; mt++) {
        #pragma unroll
        for (int nt = 0; nt < 4; nt++) {
            #pragma unroll
            for (int q = 0; q < 4; q++) {
                acc[mt][nt][q] = 0.f;
            }
        }
    }

    // prologue prefetch chunk 0
    {
        const int k0 = 0;
        cpa16(&Ah[0][far_][fac], g_w1h + (cob + far_) * CIN + k0 + fac);
        cpa16(&Al[0][far_][fac], g_w1l + (cob + far_) * CIN + k0 + fac);
        #pragma unroll
        for (int i = 0; i < 2; i++) {
            int e = t + i * 256;
            int r = e >> 4;
            int c8 = (e & 15) * 8;
            cpa16(&Bh[0][r][c8], xh + (k0 + r) * HW + p0 + c8);
            cpa16(&Bl[0][r][c8], xl + (k0 + r) * HW + p0 + c8);
        }
        cpa_commit();
    }

    for (int kc = 0; kc < 16; kc++) {
        const int s = kc & 1;
        if (kc < 15) {
            const int k0 = (kc + 1) * 32;
            cpa16(&Ah[s ^ 1][far_][fac], g_w1h + (cob + far_) * CIN + k0 + fac);
            cpa16(&Al[s ^ 1][far_][fac], g_w1l + (cob + far_) * CIN + k0 + fac);
            #pragma unroll
            for (int i = 0; i < 2; i++) {
                int e = t + i * 256;
                int r = e >> 4;
                int c8 = (e & 15) * 8;
                cpa16(&Bh[s ^ 1][r][c8], xh + (k0 + r) * HW + p0 + c8);
                cpa16(&Bl[s ^ 1][r][c8], xl + (k0 + r) * HW + p0 + c8);
            }
        }
        cpa_commit();
        cpa_wait1();
        __syncthreads();
        #pragma unroll
        for (int ks = 0; ks < 2; ks++) {
            const int kb = ks * 16;
            unsigned ah[2][4];
            unsigned al[2][4];
            unsigned bh[4][2];
            unsigned bl[4][2];
            #pragma unroll
            for (int mt = 0; mt < 2; mt++) {
                load_a_frag(ah[mt], &Ah[s][0][0], WPIT, m0 + mt * 16, kb, lane);
                load_a_frag(al[mt], &Al[s][0][0], WPIT, m0 + mt * 16, kb, lane);
            }
            #pragma unroll
            for (int hf = 0; hf < 2; hf++) {
                load_b_frag(bh[hf * 2], bh[hf * 2 + 1], &Bh[s][0][0], BPIT128, kb, n0 + hf * 16, lane);
                load_b_frag(bl[hf * 2], bl[hf * 2 + 1], &Bl[s][0][0], BPIT128, kb, n0 + hf * 16, lane);
            }
            #pragma unroll
            for (int mt = 0; mt < 2; mt++) {
                #pragma unroll
                for (int nt = 0; nt < 4; nt++) {
                    mma16816(acc[mt][nt], ah[mt], bh[nt]);
                    mma16816(acc[mt][nt], ah[mt], bl[nt]);
                    mma16816(acc[mt][nt], al[mt], bh[nt]);
                }
            }
        }
        __syncthreads();
    }
    #pragma unroll
    for (int mt = 0; mt < 2; mt++) {
        int co = cob + m0 + mt * 16 + (lane >> 2);
        float bv0 = bias[co];
        float bv8 = bias[co + 8];
        #pragma unroll
        for (int nt = 0; nt < 4; nt++) {
            int p = p0 + n0 + nt * 8 + 2 * (lane & 3);
            float2 v0;
            v0.x = acc[mt][nt][0] + bv0;
            v0.y = acc[mt][nt][1] + bv0;
            float2 v1;
            v1.x = acc[mt][nt][2] + bv8;
            v1.y = acc[mt][nt][3] + bv8;
            *(float2*)&g_f1[(bz * C1 + co) * HW + p] = v0;
            *(float2*)&g_f1[(bz * C1 + co + 8) * HW + p] = v1;
        }
    }
}

// ---------------- BN2 apply + zero pad ----------------
__global__ void pad_bn2_kernel() {
    int i = blockIdx.x * blockDim.x + threadIdx.x;
    if (i >= BATCH * C1 * HPWP) {
        return;
    }
    int pp = i % HPWP;
    int bc = i / HPWP;
    int c = bc % C1;
    int y = pp / HP;
    int xx = pp % HP;
    float v = 0.f;
    if (y >= 1 && y <= H && xx >= 1 && xx <= W) {
        v = fmaf(g_a2[c], g_f1[bc * HW + (y - 1) * W + (xx - 1)], g_b2[c]);
    }
    g_f2[i] = v;
    g_f2p[i] = packsplit(v);
}

// ---------------- offconv: 32(co) x 128(px), pipelined ----------------
__global__ __launch_bounds__(256) void offconv_kernel() {
    __shared__ unsigned short Ah[2][32][WPIT];
    __shared__ unsigned short Al[2][32][WPIT];
    __shared__ unsigned short Bh[2][32][BPIT128];
    __shared__ unsigned short Bl[2][32][BPIT128];
    const int bz = blockIdx.z;
    const int p0 = blockIdx.x * 128;
    const int t = threadIdx.x;
    const int lane = t & 31;
    const int wid = t >> 5;
    const int n0 = wid * 16;
    const unsigned* __restrict__ f2pb = g_f2p + (size_t)bz * C1 * HPWP;

    // fill coords
    const int tt = t & 127;
    const int far_ = tt >> 2;          // A row 0..31
    const int fac = (tt & 3) * 8;
    const int bj = t & 127;
    const int bk0 = t >> 7;            // 0..1
    const int bpy = (p0 + bj) / W;
    const int bpx = (p0 + bj) % W;
    const int boff = bpy * HP + bpx;

    float acc[2][2][4];
    #pragma unroll
    for (int mt = 0; mt < 2; mt++) {
        #pragma unroll
        for (int nt = 0; nt < 2; nt++) {
            #pragma unroll
            for (int q = 0; q < 4; q++) {
                acc[mt][nt][q] = 0.f;
            }
        }
    }

    unsigned nb[16];
    // prologue: chunk 0 (tap 0, ci0 0)
    {
        const unsigned* src = f2pb + boff;   // dr=0, dc=0
        #pragma unroll
        for (int i = 0; i < 16; i++) {
            int kk = bk0 + 2 * i;
            nb[i] = src[kk * HPWP];
        }
        if (t < 128) {
            cpa16(&Ah[0][far_][fac], g_w6h + far_ * KTOT + 0 + fac);
        } else {
            cpa16(&Al[0][far_][fac], g_w6l + far_ * KTOT + 0 + fac);
        }
        cpa_commit();
    }

    for (int cc = 0; cc < 72; cc++) {
        const int s = cc & 1;
        cpa_wait0();
        #pragma unroll
        for (int i = 0; i < 16; i++) {
            int kk = bk0 + 2 * i;
            unsigned w = nb[i];
            Bh[s][kk][bj] = (unsigned short)(w & 0xffffu);
            Bl[s][kk][bj] = (unsigned short)(w >> 16);
        }
        __syncthreads();
        if (cc < 71) {
            const int nc = cc + 1;
            const int tap = nc >> 3;
            const int ci0 = (nc & 7) * 32;
            const int dr = tap / 3;
            const int dc = tap % 3;
            const int kg = tap * C1 + ci0;
            const unsigned* src = f2pb + boff + dr * HP + dc + ci0 * HPWP;
            #pragma unroll
            for (int i = 0; i < 16; i++) {
                int kk = bk0 + 2 * i;
                nb[i] = src[kk * HPWP];
            }
            if (t < 128) {
                cpa16(&Ah[s ^ 1][far_][fac], g_w6h + far_ * KTOT + kg + fac);
            } else {
                cpa16(&Al[s ^ 1][far_][fac], g_w6l + far_ * KTOT + kg + fac);
            }
        }
        cpa_commit();
        #pragma unroll
        for (int ks = 0; ks < 2; ks++) {
            const int kb = ks * 16;
            unsigned ah[2][4];
            unsigned al[2][4];
            unsigned bh[2][2];
            unsigned bl[2][2];
            #pragma unroll
            for (int mt = 0; mt < 2; mt++) {
                load_a_frag(ah[mt], &Ah[s][0][0], WPIT, mt * 16, kb, lane);
                load_a_frag(al[mt], &Al[s][0][0], WPIT, mt * 16, kb, lane);
            }
            load_b_frag(bh[0], bh[1], &Bh[s][0][0], BPIT128, kb, n0, lane);
            load_b_frag(bl[0], bl[1], &Bl[s][0][0], BPIT128, kb, n0, lane);
            #pragma unroll
            for (int mt = 0; mt < 2; mt++) {
                #pragma unroll
                for (int nt = 0; nt < 2; nt++) {
                    mma16816(acc[mt][nt], ah[mt], bh[nt]);
                    mma16816(acc[mt][nt], ah[mt], bl[nt]);
                    mma16816(acc[mt][nt], al[mt], bh[nt]);
                }
            }
        }
        __syncthreads();
    }
    #pragma unroll
    for (int mt = 0; mt < 2; mt++) {
        #pragma unroll
        for (int hf = 0; hf < 2; hf++) {
            int co = mt * 16 + hf * 8 + (lane >> 2);
            if (co < COFF) {
                float bv = g_biasC[co];
                #pragma unroll
                for (int nt = 0; nt < 2; nt++) {
                    int p = p0 + n0 + nt * 8 + 2 * (lane & 3);
                    #pragma unroll
                    for (int q = 0; q < 2; q++) {
                        float v = acc[mt][nt][hf * 2 + q] + bv;
                        if (co >= 18 && co < 27) {
                            v = 1.f / (1.f + expf(-v));
                        } else if (co == 27) {
                            v = 2.f / (1.f + expf(-v));
                        }
                        g_off[(bz * COFF + co) * HW + p + q] = v;
                    }
                }
            }
        }
    }
}

// ---------------- deform: 64(o) x 64(px), pipelined gather ----------------
__global__ __launch_bounds__(256) void deform_kernel(float* __restrict__ out) {
    __shared__ unsigned short Ah[2][64][WPIT];
    __shared__ unsigned short Al[2][64][WPIT];
    __shared__ unsigned short Bh[2][32][BPIT64];
    __shared__ unsigned short Bl[2][32][BPIT64];
    __shared__ float gwS[576][4];
    __shared__ int giS[576][4];
    const int bz = blockIdx.z;
    const int p0 = blockIdx.x * 64;
    const int t = threadIdx.x;
    const int lane = t & 31;
    const int wid = t >> 5;
    const int m0 = (wid >> 2) * 32;
    const int n0 = (wid & 3) * 16;
    const float* __restrict__ offb = g_off + (size_t)bz * COFF * HW;
    const float* __restrict__ f2b = g_f2 + (size_t)bz * C1 * HPWP;

    for (int e = t; e < 576; e += 256) {
        int j = e / NS;
        int n = e % NS;
        int p = p0 + j;
        int row = p / W;
        int col = p % W;
        float s = offb[27 * HW + p];
        float m = offb[(18 + n) * HW + p];
        float ox = offb[n * HW + p];
        float oy = offb[(9 + n) * HW + p];
        float fpx = (float)(row + 1) + 6.f * s * (float)(n / 3 - 1) + ox;
        float fpy = (float)(col + 1) + 6.f * s * (float)(n % 3 - 1) + oy;
        float fx = floorf(fpx);
        float fy = floorf(fpy);
        float qxl = fminf(fmaxf(fx, 0.f), 97.f);
        float qxr = fminf(fmaxf(fx + 1.f, 0.f), 97.f);
        float qyl = fminf(fmaxf(fy, 0.f), 97.f);
        float qyr = fminf(fmaxf(fy + 1.f, 0.f), 97.f);
        float pxc = fminf(fmaxf(fpx, 0.f), 97.f);
        float pyc = fminf(fmaxf(fpy, 0.f), 97.f);
        float wxl = 1.f + (qxl - pxc);
        float wxr = 1.f - (qxr - pxc);
        float wyl = 1.f + (qyl - pyc);
        float wyr = 1.f - (qyr - pyc);
        gwS[e][0] = wxl * wyl * m;
        gwS[e][1] = wxr * wyr * m;
        gwS[e][2] = wxl * wyr * m;
        gwS[e][3] = wxr * wyl * m;
        int ixl = (int)qxl * HP;
        int ixr = (int)qxr * HP;
        int iyl = (int)qyl;
        int iyr = (int)qyr;
        giS[e][0] = ixl + iyl;
        giS[e][1] = ixr + iyr;
        giS[e][2] = ixl + iyr;
        giS[e][3] = ixr + iyl;
    }
    __syncthreads();

    // fill coords
    const int far_ = t >> 2;           // A row 0..63
    const int fac = (t & 3) * 8;
    const int bj = t & 63;
    const int bk0 = t >> 6;            // 0..3

    float acc[2][2][4];
    #pragma unroll
    for (int mt = 0; mt < 2; mt++) {
        #pragma unroll
        for (int nt = 0; nt < 2; nt++) {
            #pragma unroll
            for (int q = 0; q < 4; q++) {
                acc[mt][nt][q] = 0.f;
            }
        }
    }

    float nb[32];
    float4 cw4;
    // prologue: chunk 0 (n=0, ci0=0)
    {
        int g = bj * NS;
        float4 w4 = *(const float4*)gwS[g];
        int4 i4 = *(const int4*)giS[g];
        #pragma unroll
        for (int i = 0; i < 8; i++) {
            int kk = bk0 + 4 * i;
            const float* pl = f2b + kk * HPWP;
            nb[i * 4 + 0] = pl[i4.x];
            nb[i * 4 + 1] = pl[i4.y];
            nb[i * 4 + 2] = pl[i4.z];
            nb[i * 4 + 3] = pl[i4.w];
        }
        cw4 = w4;
        cpa16(&Ah[0][far_][fac], g_w7h + far_ * KTOT + 0 + fac);
        cpa16(&Al[0][far_][fac], g_w7l + far_ * KTOT + 0 + fac);
        cpa_commit();
    }

    for (int cc = 0; cc < 72; cc++) {
        const int s = cc & 1;
        cpa_wait0();
        #pragma unroll
        for (int i = 0; i < 8; i++) {
            int kk = bk0 + 4 * i;
            float v = cw4.x * nb[i * 4 + 0] + cw4.y * nb[i * 4 + 1]
                    + cw4.z * nb[i * 4 + 2] + cw4.w * nb[i * 4 + 3];
            unsigned pv = packsplit(v);
            Bh[s][kk][bj] = (unsigned short)(pv & 0xffffu);
            Bl[s][kk][bj] = (unsigned short)(pv >> 16);
        }
        __syncthreads();
        if (cc < 71) {
            const int nc = cc + 1;
            const int nn = nc >> 3;
            const int ci0 = (nc & 7) * 32;
            const int kg = nn * C1 + ci0;
            int g = bj * NS + nn;
            float4 w4 = *(const float4*)gwS[g];
            int4 i4 = *(const int4*)giS[g];
            const float* plb = f2b + ci0 * HPWP;
            #pragma unroll
            for (int i = 0; i < 8; i++) {
                int kk = bk0 + 4 * i;
                const float* pl = plb + kk * HPWP;
                nb[i * 4 + 0] = pl[i4.x];
                nb[i * 4 + 1] = pl[i4.y];
                nb[i * 4 + 2] = pl[i4.z];
                nb[i * 4 + 3] = pl[i4.w];
            }
            cw4 = w4;
            cpa16(&Ah[s ^ 1][far_][fac], g_w7h + far_ * KTOT + kg + fac);
            cpa16(&Al[s ^ 1][far_][fac], g_w7l + far_ * KTOT + kg + fac);
        }
        cpa_commit();
        #pragma unroll
        for (int ks = 0; ks < 2; ks++) {
            const int kb = ks * 16;
            unsigned ah[2][4];
            unsigned al[2][4];
            unsigned bh[2][2];
            unsigned bl[2][2];
            #pragma unroll
            for (int mt = 0; mt < 2; mt++) {
                load_a_frag(ah[mt], &Ah[s][0][0], WPIT, m0 + mt * 16, kb, lane);
                load_a_frag(al[mt], &Al[s][0][0], WPIT, m0 + mt * 16, kb, lane);
            }
            load_b_frag(bh[0], bh[1], &Bh[s][0][0], BPIT64, kb, n0, lane);
            load_b_frag(bl[0], bl[1], &Bl[s][0][0], BPIT64, kb, n0, lane);
            #pragma unroll
            for (int mt = 0; mt < 2; mt++) {
                #pragma unroll
                for (int nt = 0; nt < 2; nt++) {
                    mma16816(acc[mt][nt], ah[mt], bh[nt]);
                    mma16816(acc[mt][nt], ah[mt], bl[nt]);
                    mma16816(acc[mt][nt], al[mt], bh[nt]);
                }
            }
        }
        __syncthreads();
    }
    #pragma unroll
    for (int mt = 0; mt < 2; mt++) {
        int o = m0 + mt * 16 + (lane >> 2);
        #pragma unroll
        for (int nt = 0; nt < 2; nt++) {
            int p = p0 + n0 + nt * 8 + 2 * (lane & 3);
            float2 v0;
            v0.x = acc[mt][nt][0];
            v0.y = acc[mt][nt][1];
            float2 v1;
            v1.x = acc[mt][nt][2];
            v1.y = acc[mt][nt][3];
            *(float2*)&out[(bz * C2 + o) * HW + p] = v0;
            *(float2*)&out[(bz * C2 + o + 8) * HW + p] = v1;
        }
    }
}

// ---------------- launch ----------------
extern "C" void kernel_launch(void* const* d_in, const int* in_sizes, int n_in,
                              void* d_out, int out_size) {
    const float* x = (const float*)d_in[0];
    const float* bn1_g = (const float*)d_in[1];
    const float* bn1_b = (const float*)d_in[2];
    const float* w1 = (const float*)d_in[3];
    const float* b1 = (const float*)d_in[4];
    const float* bn2_g = (const float*)d_in[5];
    const float* bn2_b = (const float*)d_in[6];
    const float* pw = (const float*)d_in[7];
    const float* pb = (const float*)d_in[8];
    const float* mw = (const float*)d_in[9];
    const float* mb = (const float*)d_in[10];
    const float* dw = (const float*)d_in[11];
    const float* db = (const float*)d_in[12];
    const float* w7 = (const float*)d_in[13];
    float* out = (float*)d_out;

    prep_kernel<<<(C2 * KTOT + 255) / 256, 256>>>(w1, pw, pb, mw, mb, dw, db, w7);
    bn1_stats_kernel<<<CIN, 256>>>(x, bn1_g, bn1_b);
    xcvt_kernel<<<(BATCH * CIN * HW / 4 + 255) / 256, 256>>>(x);
    conv1_kernel<<<dim3(HW / 128, C1 / 64, BATCH), 256>>>(b1);
    bn2_stats_kernel<<<C1, 256>>>(bn2_g, bn2_b);
    pad_bn2_kernel<<<(BATCH * C1 * HPWP + 255) / 256, 256>>>();
    offconv_kernel<<<dim3(HW / 128, 1, BATCH), 256>>>();
    deform_kernel<<<dim3(HW / 64, 1, BATCH), 256>>>(out);
}

// round 7
// speedup vs baseline: 1.9832x; 1.0129x over previous
#include <cuda_runtime.h>
#include <cuda_fp16.h>
#include <math.h>

#define H   96
#define W   96
#define HW  9216
#define HP  98
#define HPWP 9604
#define CIN 512
#define C1  256
#define C2  64
#define BATCH 2
#define NS  9
#define COFF 28
#define KTOT (C1*NS)
#define EPSV 1e-5f
#define F2TOT (BATCH * C1 * HPWP)

#define WPIT 40
#define BPIT128 136

// ---------------- scratch ----------------
__device__ float g_f1[BATCH * C1 * HW];
__device__ float2 g_f2d[F2TOT + 2];                 // (v[i], v[i+1]) pairs, deform gather
__device__ unsigned g_f2p[F2TOT];                   // packed fp16 hi|lo, offconv B
__device__ unsigned short g_xh[BATCH * CIN * HW];   // fp16 hi of BN1+ReLU(x)
__device__ unsigned short g_xl[BATCH * CIN * HW];   // fp16 lo
__device__ float g_off[BATCH * COFF * HW];
__device__ float g_a1[CIN];
__device__ float g_b1[CIN];
__device__ float g_a2[C1];
__device__ float g_b2[C1];
__device__ float g_biasC[32];
__device__ unsigned short g_w1h[C1 * CIN];
__device__ unsigned short g_w1l[C1 * CIN];
__device__ unsigned short g_w6h[32 * KTOT];
__device__ unsigned short g_w6l[32 * KTOT];
__device__ unsigned short g_w7h[C2 * KTOT];
__device__ unsigned short g_w7l[C2 * KTOT];

// ---------------- helpers ----------------
__device__ __forceinline__ void splith(float v, unsigned short* hp, unsigned short* lp) {
    __half h = __float2half(v);
    float hf = __half2float(h);
    __half l = __float2half(v - hf);
    *hp = __half_as_ushort(h);
    *lp = __half_as_ushort(l);
}

__device__ __forceinline__ unsigned packsplit(float v) {
    __half h = __float2half(v);
    float hf = __half2float(h);
    __half l = __float2half(v - hf);
    return (unsigned)__half_as_ushort(h) | ((unsigned)__half_as_ushort(l) << 16);
}

__device__ __forceinline__ unsigned smaddr(const void* p) {
    return (unsigned)__cvta_generic_to_shared(p);
}

__device__ __forceinline__ void cpa16(void* dst, const void* src) {
    asm volatile("cp.async.cg.shared.global [%0], [%1], 16;"
                 :: "r"(smaddr(dst)), "l"(src));
}
__device__ __forceinline__ void cpa_commit() {
    asm volatile("cp.async.commit_group;");
}
__device__ __forceinline__ void cpa_wait0() {
    asm volatile("cp.async.wait_group 0;");
}
__device__ __forceinline__ void cpa_wait1() {
    asm volatile("cp.async.wait_group 1;");
}

__device__ __forceinline__ void ldsm4(unsigned* r, unsigned a) {
    asm volatile("ldmatrix.sync.aligned.m8n8.x4.shared.b16 {%0,%1,%2,%3}, [%4];"
                 : "=r"(r[0]), "=r"(r[1]), "=r"(r[2]), "=r"(r[3])
                 : "r"(a));
}

__device__ __forceinline__ void ldsm4t(unsigned* r, unsigned a) {
    asm volatile("ldmatrix.sync.aligned.m8n8.x4.trans.shared.b16 {%0,%1,%2,%3}, [%4];"
                 : "=r"(r[0]), "=r"(r[1]), "=r"(r[2]), "=r"(r[3])
                 : "r"(a));
}

__device__ __forceinline__ void mma16816(float* c, const unsigned* a, const unsigned* b) {
    asm volatile("mma.sync.aligned.m16n8k16.row.col.f32.f16.f16.f32 "
                 "{%0,%1,%2,%3}, {%4,%5,%6,%7}, {%8,%9}, {%0,%1,%2,%3};"
                 : "+f"(c[0]), "+f"(c[1]), "+f"(c[2]), "+f"(c[3])
                 : "r"(a[0]), "r"(a[1]), "r"(a[2]), "r"(a[3]), "r"(b[0]), "r"(b[1]));
}

__device__ __forceinline__ void load_a_frag(unsigned* a, const unsigned short* base,
                                            int pitch, int row0, int kb, int lane) {
    const unsigned short* p = base + (row0 + (lane & 15)) * pitch + kb + ((lane >> 4) * 8);
    ldsm4(a, smaddr(p));
}

__device__ __forceinline__ void load_b_frag(unsigned b0[2], unsigned b1[2],
                                            const unsigned short* base,
                                            int pitch, int kb, int n0, int lane) {
    unsigned tmp[4];
    const unsigned short* p = base + (kb + (lane & 15)) * pitch + n0 + ((lane >> 4) * 8);
    ldsm4t(tmp, smaddr(p));
    b0[0] = tmp[0];
    b0[1] = tmp[1];
    b1[0] = tmp[2];
    b1[1] = tmp[3];
}

// ---------------- weight prep ----------------
__global__ void prep_kernel(const float* __restrict__ w1,
                            const float* __restrict__ pw, const float* __restrict__ pb,
                            const float* __restrict__ mw, const float* __restrict__ mb,
                            const float* __restrict__ dw, const float* __restrict__ db,
                            const float* __restrict__ w7) {
    int i = blockIdx.x * blockDim.x + threadIdx.x;
    if (i < C1 * CIN) {
        splith(w1[i], &g_w1h[i], &g_w1l[i]);
    }
    if (i < 32 * KTOT) {
        int co = i / KTOT;
        int k = i % KTOT;
        int r = k / C1;
        int ci = k % C1;
        float v = 0.f;
        if (co < 18) {
            v = pw[(co * C1 + ci) * NS + r];
        } else if (co < 27) {
            v = mw[((co - 18) * C1 + ci) * NS + r];
        } else if (co == 27) {
            v = dw[ci * NS + r];
        }
        splith(v, &g_w6h[i], &g_w6l[i]);
    }
    if (i < C2 * KTOT) {
        int o = i / KTOT;
        int k = i % KTOT;
        int n = k / C1;
        int ci = k % C1;
        splith(w7[(o * C1 + ci) * NS + n], &g_w7h[i], &g_w7l[i]);
    }
    if (i < 32) {
        float v = 0.f;
        if (i < 18) {
            v = pb[i];
        } else if (i < 27) {
            v = mb[i - 18];
        } else if (i == 27) {
            v = db[0];
        }
        g_biasC[i] = v;
    }
}

// ---------------- BN stats ----------------
__device__ __forceinline__ void bn_reduce(float s, float s2, float* sh,
                                          float gamma, float beta,
                                          float* a_out, float* b_out, int c) {
    sh[threadIdx.x] = s;
    sh[256 + threadIdx.x] = s2;
    __syncthreads();
    for (int st = 128; st > 0; st >>= 1) {
        if (threadIdx.x < st) {
            sh[threadIdx.x] += sh[threadIdx.x + st];
            sh[256 + threadIdx.x] += sh[256 + threadIdx.x + st];
        }
        __syncthreads();
    }
    if (threadIdx.x == 0) {
        const float inv = 1.f / (float)(BATCH * HW);
        float mean = sh[0] * inv;
        float var = sh[256] * inv - mean * mean;
        float a = gamma / sqrtf(var + EPSV);
        a_out[c] = a;
        b_out[c] = beta - mean * a;
    }
}

__global__ void bn1_stats_kernel(const float* __restrict__ x,
                                 const float* __restrict__ gamma,
                                 const float* __restrict__ beta) {
    __shared__ float sh[512];
    int c = blockIdx.x;
    float s = 0.f;
    float s2 = 0.f;
    #pragma unroll
    for (int bb = 0; bb < BATCH; bb++) {
        const float4* pl = (const float4*)(x + ((size_t)bb * CIN + c) * HW);
        for (int q = threadIdx.x; q < HW / 4; q += 256) {
            float4 v = pl[q];
            s += v.x + v.y + v.z + v.w;
            s2 += v.x * v.x + v.y * v.y + v.z * v.z + v.w * v.w;
        }
    }
    bn_reduce(s, s2, sh, gamma[c], beta[c], g_a1, g_b1, c);
}

__global__ void bn2_stats_kernel(const float* __restrict__ gamma,
                                 const float* __restrict__ beta) {
    __shared__ float sh[512];
    int c = blockIdx.x;
    float s = 0.f;
    float s2 = 0.f;
    #pragma unroll
    for (int bb = 0; bb < BATCH; bb++) {
        const float4* pl = (const float4*)(g_f1 + ((size_t)bb * C1 + c) * HW);
        for (int q = threadIdx.x; q < HW / 4; q += 256) {
            float4 v = pl[q];
            s += v.x + v.y + v.z + v.w;
            s2 += v.x * v.x + v.y * v.y + v.z * v.z + v.w * v.w;
        }
    }
    bn_reduce(s, s2, sh, gamma[c], beta[c], g_a2, g_b2, c);
}

// ---------------- xcvt ----------------
__global__ void xcvt_kernel(const float* __restrict__ x) {
    int i4 = blockIdx.x * blockDim.x + threadIdx.x;
    if (i4 >= BATCH * CIN * HW / 4) {
        return;
    }
    int c = (i4 * 4 / HW) % CIN;
    float a = g_a1[c];
    float b = g_b1[c];
    float4 v = ((const float4*)x)[i4];
    ushort4 oh;
    ushort4 ol;
    splith(fmaxf(fmaf(a, v.x, b), 0.f), &oh.x, &ol.x);
    splith(fmaxf(fmaf(a, v.y, b), 0.f), &oh.y, &ol.y);
    splith(fmaxf(fmaf(a, v.z, b), 0.f), &oh.z, &ol.z);
    splith(fmaxf(fmaf(a, v.w, b), 0.f), &oh.w, &ol.w);
    ((ushort4*)g_xh)[i4] = oh;
    ((ushort4*)g_xl)[i4] = ol;
}

// ---------------- conv1: 64(co) x 128(px), cp.async double-buffered ----------
__global__ __launch_bounds__(256) void conv1_kernel(const float* __restrict__ bias) {
    __shared__ unsigned short Ah[2][64][WPIT];
    __shared__ unsigned short Al[2][64][WPIT];
    __shared__ unsigned short Bh[2][32][BPIT128];
    __shared__ unsigned short Bl[2][32][BPIT128];
    const int bz = blockIdx.z;
    const int p0 = blockIdx.x * 128;
    const int cob = blockIdx.y * 64;
    const int t = threadIdx.x;
    const int lane = t & 31;
    const int wid = t >> 5;
    const int m0 = (wid >> 2) * 32;
    const int n0 = (wid & 3) * 32;
    const unsigned short* __restrict__ xh = g_xh + (size_t)bz * CIN * HW;
    const unsigned short* __restrict__ xl = g_xl + (size_t)bz * CIN * HW;

    const int far_ = t >> 2;
    const int fac = (t & 3) * 8;

    float acc[2][4][4];
    #pragma unroll
    for (int mt = 0; mt < 2; mt++) {
        #pragma unroll
        for (int nt = 0; nt < 4; nt++) {
            #pragma unroll
            for (int q = 0; q < 4; q++) {
                acc[mt][nt][q] = 0.f;
            }
        }
    }

    {
        cpa16(&Ah[0][far_][fac], g_w1h + (cob + far_) * CIN + fac);
        cpa16(&Al[0][far_][fac], g_w1l + (cob + far_) * CIN + fac);
        #pragma unroll
        for (int i = 0; i < 2; i++) {
            int e = t + i * 256;
            int r = e >> 4;
            int c8 = (e & 15) * 8;
            cpa16(&Bh[0][r][c8], xh + r * HW + p0 + c8);
            cpa16(&Bl[0][r][c8], xl + r * HW + p0 + c8);
        }
        cpa_commit();
    }

    for (int kc = 0; kc < 16; kc++) {
        const int s = kc & 1;
        if (kc < 15) {
            const int k0 = (kc + 1) * 32;
            cpa16(&Ah[s ^ 1][far_][fac], g_w1h + (cob + far_) * CIN + k0 + fac);
            cpa16(&Al[s ^ 1][far_][fac], g_w1l + (cob + far_) * CIN + k0 + fac);
            #pragma unroll
            for (int i = 0; i < 2; i++) {
                int e = t + i * 256;
                int r = e >> 4;
                int c8 = (e & 15) * 8;
                cpa16(&Bh[s ^ 1][r][c8], xh + (k0 + r) * HW + p0 + c8);
                cpa16(&Bl[s ^ 1][r][c8], xl + (k0 + r) * HW + p0 + c8);
            }
        }
        cpa_commit();
        cpa_wait1();
        __syncthreads();
        #pragma unroll
        for (int ks = 0; ks < 2; ks++) {
            const int kb = ks * 16;
            unsigned ah[2][4];
            unsigned al[2][4];
            unsigned bh[4][2];
            unsigned bl[4][2];
            #pragma unroll
            for (int mt = 0; mt < 2; mt++) {
                load_a_frag(ah[mt], &Ah[s][0][0], WPIT, m0 + mt * 16, kb, lane);
                load_a_frag(al[mt], &Al[s][0][0], WPIT, m0 + mt * 16, kb, lane);
            }
            #pragma unroll
            for (int hf = 0; hf < 2; hf++) {
                load_b_frag(bh[hf * 2], bh[hf * 2 + 1], &Bh[s][0][0], BPIT128, kb, n0 + hf * 16, lane);
                load_b_frag(bl[hf * 2], bl[hf * 2 + 1], &Bl[s][0][0], BPIT128, kb, n0 + hf * 16, lane);
            }
            #pragma unroll
            for (int mt = 0; mt < 2; mt++) {
                #pragma unroll
                for (int nt = 0; nt < 4; nt++) {
                    mma16816(acc[mt][nt], ah[mt], bh[nt]);
                    mma16816(acc[mt][nt], ah[mt], bl[nt]);
                    mma16816(acc[mt][nt], al[mt], bh[nt]);
                }
            }
        }
        __syncthreads();
    }
    #pragma unroll
    for (int mt = 0; mt < 2; mt++) {
        int co = cob + m0 + mt * 16 + (lane >> 2);
        float bv0 = bias[co];
        float bv8 = bias[co + 8];
        #pragma unroll
        for (int nt = 0; nt < 4; nt++) {
            int p = p0 + n0 + nt * 8 + 2 * (lane & 3);
            float2 v0;
            v0.x = acc[mt][nt][0] + bv0;
            v0.y = acc[mt][nt][1] + bv0;
            float2 v1;
            v1.x = acc[mt][nt][2] + bv8;
            v1.y = acc[mt][nt][3] + bv8;
            *(float2*)&g_f1[(bz * C1 + co) * HW + p] = v0;
            *(float2*)&g_f1[(bz * C1 + co + 8) * HW + p] = v1;
        }
    }
}

// ---------------- BN2 apply + zero pad (pair + packed) ----------------
__device__ __forceinline__ float bn2_at(int j) {
    int pp = j % HPWP;
    int bc = j / HPWP;
    int c = bc % C1;
    int y = pp / HP;
    int xx = pp % HP;
    float v = 0.f;
    if (y >= 1 && y <= H && xx >= 1 && xx <= W) {
        v = fmaf(g_a2[c], g_f1[bc * HW + (y - 1) * W + (xx - 1)], g_b2[c]);
    }
    return v;
}

__global__ void pad_bn2_kernel() {
    int i = blockIdx.x * blockDim.x + threadIdx.x;
    if (i >= F2TOT) {
        return;
    }
    float v0 = bn2_at(i);
    float v1 = 0.f;
    if (i + 1 < F2TOT) {
        v1 = bn2_at(i + 1);
    }
    g_f2d[i] = make_float2(v0, v1);
    g_f2p[i] = packsplit(v0);
}

// ---------------- offconv: 32(co) x 128(px), pipelined ----------------
__global__ __launch_bounds__(256) void offconv_kernel() {
    __shared__ unsigned short Ah[2][32][WPIT];
    __shared__ unsigned short Al[2][32][WPIT];
    __shared__ unsigned short Bh[2][32][BPIT128];
    __shared__ unsigned short Bl[2][32][BPIT128];
    const int bz = blockIdx.z;
    const int p0 = blockIdx.x * 128;
    const int t = threadIdx.x;
    const int lane = t & 31;
    const int wid = t >> 5;
    const int n0 = wid * 16;
    const unsigned* __restrict__ f2pb = g_f2p + (size_t)bz * C1 * HPWP;

    const int tt = t & 127;
    const int far_ = tt >> 2;
    const int fac = (tt & 3) * 8;
    const int bj = t & 127;
    const int bk0 = t >> 7;
    const int bpy = (p0 + bj) / W;
    const int bpx = (p0 + bj) % W;
    const int boff = bpy * HP + bpx;

    float acc[2][2][4];
    #pragma unroll
    for (int mt = 0; mt < 2; mt++) {
        #pragma unroll
        for (int nt = 0; nt < 2; nt++) {
            #pragma unroll
            for (int q = 0; q < 4; q++) {
                acc[mt][nt][q] = 0.f;
            }
        }
    }

    unsigned nb[16];
    {
        const unsigned* src = f2pb + boff;
        #pragma unroll
        for (int i = 0; i < 16; i++) {
            int kk = bk0 + 2 * i;
            nb[i] = src[kk * HPWP];
        }
        if (t < 128) {
            cpa16(&Ah[0][far_][fac], g_w6h + far_ * KTOT + fac);
        } else {
            cpa16(&Al[0][far_][fac], g_w6l + far_ * KTOT + fac);
        }
        cpa_commit();
    }

    for (int cc = 0; cc < 72; cc++) {
        const int s = cc & 1;
        cpa_wait0();
        #pragma unroll
        for (int i = 0; i < 16; i++) {
            int kk = bk0 + 2 * i;
            unsigned w = nb[i];
            Bh[s][kk][bj] = (unsigned short)(w & 0xffffu);
            Bl[s][kk][bj] = (unsigned short)(w >> 16);
        }
        __syncthreads();
        if (cc < 71) {
            const int nc = cc + 1;
            const int tap = nc >> 3;
            const int ci0 = (nc & 7) * 32;
            const int dr = tap / 3;
            const int dc = tap % 3;
            const int kg = tap * C1 + ci0;
            const unsigned* src = f2pb + boff + dr * HP + dc + ci0 * HPWP;
            #pragma unroll
            for (int i = 0; i < 16; i++) {
                int kk = bk0 + 2 * i;
                nb[i] = src[kk * HPWP];
            }
            if (t < 128) {
                cpa16(&Ah[s ^ 1][far_][fac], g_w6h + far_ * KTOT + kg + fac);
            } else {
                cpa16(&Al[s ^ 1][far_][fac], g_w6l + far_ * KTOT + kg + fac);
            }
        }
        cpa_commit();
        #pragma unroll
        for (int ks = 0; ks < 2; ks++) {
            const int kb = ks * 16;
            unsigned ah[2][4];
            unsigned al[2][4];
            unsigned bh[2][2];
            unsigned bl[2][2];
            #pragma unroll
            for (int mt = 0; mt < 2; mt++) {
                load_a_frag(ah[mt], &Ah[s][0][0], WPIT, mt * 16, kb, lane);
                load_a_frag(al[mt], &Al[s][0][0], WPIT, mt * 16, kb, lane);
            }
            load_b_frag(bh[0], bh[1], &Bh[s][0][0], BPIT128, kb, n0, lane);
            load_b_frag(bl[0], bl[1], &Bl[s][0][0], BPIT128, kb, n0, lane);
            #pragma unroll
            for (int mt = 0; mt < 2; mt++) {
                #pragma unroll
                for (int nt = 0; nt < 2; nt++) {
                    mma16816(acc[mt][nt], ah[mt], bh[nt]);
                    mma16816(acc[mt][nt], ah[mt], bl[nt]);
                    mma16816(acc[mt][nt], al[mt], bh[nt]);
                }
            }
        }
        __syncthreads();
    }
    #pragma unroll
    for (int mt = 0; mt < 2; mt++) {
        #pragma unroll
        for (int hf = 0; hf < 2; hf++) {
            int co = mt * 16 + hf * 8 + (lane >> 2);
            if (co < COFF) {
                float bv = g_biasC[co];
                #pragma unroll
                for (int nt = 0; nt < 2; nt++) {
                    int p = p0 + n0 + nt * 8 + 2 * (lane & 3);
                    #pragma unroll
                    for (int q = 0; q < 2; q++) {
                        float v = acc[mt][nt][hf * 2 + q] + bv;
                        if (co >= 18 && co < 27) {
                            v = 1.f / (1.f + expf(-v));
                        } else if (co == 27) {
                            v = 2.f / (1.f + expf(-v));
                        }
                        g_off[(bz * COFF + co) * HW + p + q] = v;
                    }
                }
            }
        }
    }
}

// ---------------- deform: 64(o) x 128(px), separable gather, dynamic smem ----
// dyn smem layout (bytes):
//   gw  float4[1152]  @ 0       (18432)
//   gi  int2  [1152]  @ 18432   (9216)
//   Ah  us[2][64][40] @ 27648   (10240)
//   Al                @ 37888   (10240)
//   Bh  us[2][32][136]@ 48128   (17408)
//   Bl                @ 65536   (17408)  -> total 82944
#define DEF_SMEM 82944

__global__ __launch_bounds__(256) void deform_kernel(float* __restrict__ out) {
    extern __shared__ char smr[];
    float4* gwS = (float4*)smr;
    int2* giS = (int2*)(smr + 18432);
    unsigned short* AhS = (unsigned short*)(smr + 27648);
    unsigned short* AlS = (unsigned short*)(smr + 37888);
    unsigned short* BhS = (unsigned short*)(smr + 48128);
    unsigned short* BlS = (unsigned short*)(smr + 65536);

    const int bz = blockIdx.z;
    const int p0 = blockIdx.x * 128;
    const int t = threadIdx.x;
    const int lane = t & 31;
    const int wid = t >> 5;
    const int m0 = (wid >> 2) * 32;
    const int n0 = (wid & 3) * 32;
    const float* __restrict__ offb = g_off + (size_t)bz * COFF * HW;
    const float2* __restrict__ f2db = g_f2d + (size_t)bz * C1 * HPWP;

    // geometry: 128 px x 9 taps, separable bilinear
    for (int e = t; e < 128 * NS; e += 256) {
        int j = e / NS;
        int n = e % NS;
        int p = p0 + j;
        int row = p / W;
        int col = p % W;
        float s = offb[27 * HW + p];
        float m = offb[(18 + n) * HW + p];
        float ox = offb[n * HW + p];
        float oy = offb[(9 + n) * HW + p];
        float fpx = (float)(row + 1) + 6.f * s * (float)(n / 3 - 1) + ox;
        float fpy = (float)(col + 1) + 6.f * s * (float)(n % 3 - 1) + oy;
        float fx = floorf(fpx);
        float fy = floorf(fpy);
        float qxl = fminf(fmaxf(fx, 0.f), 97.f);
        float qxr = fminf(fmaxf(fx + 1.f, 0.f), 97.f);
        float qyl = fminf(fmaxf(fy, 0.f), 97.f);
        float qyr = fminf(fmaxf(fy + 1.f, 0.f), 97.f);
        float pxc = fminf(fmaxf(fpx, 0.f), 97.f);
        float pyc = fminf(fmaxf(fpy, 0.f), 97.f);
        float a0 = (1.f + (qxl - pxc)) * m;
        float a1 = (1.f - (qxr - pxc)) * m;
        float wyl = 1.f + (qyl - pyc);
        float wyr = 1.f - (qyr - pyc);
        int cyl = (int)qyl;
        int cyr = (int)qyr;
        int cy;
        float w0;
        float w1;
        if (cyr > cyl) {
            cy = cyl;
            w0 = wyl;
            w1 = wyr;
        } else if (cyl == 0) {
            cy = 0;
            w0 = wyl + wyr;
            w1 = 0.f;
        } else {
            cy = 96;
            w0 = 0.f;
            w1 = wyl + wyr;
        }
        gwS[e] = make_float4(a0, a1, w0, w1);
        giS[e] = make_int2((int)qxl * HP + cy, (int)qxr * HP + cy);
    }
    __syncthreads();

    const int far_ = t >> 2;
    const int fac = (t & 3) * 8;
    const int bj = t & 127;
    const int bk0 = t >> 7;   // 0..1; kk = bk0 + 2*i, i<16

    float acc[2][4][4];
    #pragma unroll
    for (int mt = 0; mt < 2; mt++) {
        #pragma unroll
        for (int nt = 0; nt < 4; nt++) {
            #pragma unroll
            for (int q = 0; q < 4; q++) {
                acc[mt][nt][q] = 0.f;
            }
        }
    }

    float2 nu[16];
    float2 nv[16];
    float4 cw;
    {
        int g = bj * NS;
        float4 w4 = gwS[g];
        int2 i2 = giS[g];
        #pragma unroll
        for (int i = 0; i < 16; i++) {
            int kk = bk0 + 2 * i;
            const float2* pl = f2db + kk * HPWP;
            nu[i] = pl[i2.x];
            nv[i] = pl[i2.y];
        }
        cw = w4;
        cpa16(&AhS[far_ * WPIT + fac], g_w7h + far_ * KTOT + fac);
        cpa16(&AlS[far_ * WPIT + fac], g_w7l + far_ * KTOT + fac);
        cpa_commit();
    }

    for (int cc = 0; cc < 72; cc++) {
        const int s = cc & 1;
        const int sa = s * 64 * WPIT;
        const int sb = s * 32 * BPIT128;
        cpa_wait0();
        #pragma unroll
        for (int i = 0; i < 16; i++) {
            int kk = bk0 + 2 * i;
            float t0 = cw.x * nu[i].x + cw.y * nv[i].x;
            float t1 = cw.x * nu[i].y + cw.y * nv[i].y;
            unsigned pv = packsplit(cw.z * t0 + cw.w * t1);
            BhS[sb + kk * BPIT128 + bj] = (unsigned short)(pv & 0xffffu);
            BlS[sb + kk * BPIT128 + bj] = (unsigned short)(pv >> 16);
        }
        __syncthreads();
        if (cc < 71) {
            const int nc = cc + 1;
            const int nn = nc >> 3;
            const int ci0 = (nc & 7) * 32;
            const int kg = nn * C1 + ci0;
            int g = bj * NS + nn;
            float4 w4 = gwS[g];
            int2 i2 = giS[g];
            const float2* plb = f2db + ci0 * HPWP;
            #pragma unroll
            for (int i = 0; i < 16; i++) {
                int kk = bk0 + 2 * i;
                const float2* pl = plb + kk * HPWP;
                nu[i] = pl[i2.x];
                nv[i] = pl[i2.y];
            }
            cw = w4;
            const int na = (s ^ 1) * 64 * WPIT;
            cpa16(&AhS[na + far_ * WPIT + fac], g_w7h + far_ * KTOT + kg + fac);
            cpa16(&AlS[na + far_ * WPIT + fac], g_w7l + far_ * KTOT + kg + fac);
        }
        cpa_commit();
        #pragma unroll
        for (int ks = 0; ks < 2; ks++) {
            const int kb = ks * 16;
            unsigned ah[2][4];
            unsigned al[2][4];
            unsigned bh[4][2];
            unsigned bl[4][2];
            #pragma unroll
            for (int mt = 0; mt < 2; mt++) {
                load_a_frag(ah[mt], AhS + sa, WPIT, m0 + mt * 16, kb, lane);
                load_a_frag(al[mt], AlS + sa, WPIT, m0 + mt * 16, kb, lane);
            }
            #pragma unroll
            for (int hf = 0; hf < 2; hf++) {
                load_b_frag(bh[hf * 2], bh[hf * 2 + 1], BhS + sb, BPIT128, kb, n0 + hf * 16, lane);
                load_b_frag(bl[hf * 2], bl[hf * 2 + 1], BlS + sb, BPIT128, kb, n0 + hf * 16, lane);
            }
            #pragma unroll
            for (int mt = 0; mt < 2; mt++) {
                #pragma unroll
                for (int nt = 0; nt < 4; nt++) {
                    mma16816(acc[mt][nt], ah[mt], bh[nt]);
                    mma16816(acc[mt][nt], ah[mt], bl[nt]);
                    mma16816(acc[mt][nt], al[mt], bh[nt]);
                }
            }
        }
        __syncthreads();
    }
    #pragma unroll
    for (int mt = 0; mt < 2; mt++) {
        int o = m0 + mt * 16 + (lane >> 2);
        #pragma unroll
        for (int nt = 0; nt < 4; nt++) {
            int p = p0 + n0 + nt * 8 + 2 * (lane & 3);
            float2 v0;
            v0.x = acc[mt][nt][0];
            v0.y = acc[mt][nt][1];
            float2 v1;
            v1.x = acc[mt][nt][2];
            v1.y = acc[mt][nt][3];
            *(float2*)&out[(bz * C2 + o) * HW + p] = v0;
            *(float2*)&out[(bz * C2 + o + 8) * HW + p] = v1;
        }
    }
}

// ---------------- launch ----------------
extern "C" void kernel_launch(void* const* d_in, const int* in_sizes, int n_in,
                              void* d_out, int out_size) {
    const float* x = (const float*)d_in[0];
    const float* bn1_g = (const float*)d_in[1];
    const float* bn1_b = (const float*)d_in[2];
    const float* w1 = (const float*)d_in[3];
    const float* b1 = (const float*)d_in[4];
    const float* bn2_g = (const float*)d_in[5];
    const float* bn2_b = (const float*)d_in[6];
    const float* pw = (const float*)d_in[7];
    const float* pb = (const float*)d_in[8];
    const float* mw = (const float*)d_in[9];
    const float* mb = (const float*)d_in[10];
    const float* dw = (const float*)d_in[11];
    const float* db = (const float*)d_in[12];
    const float* w7 = (const float*)d_in[13];
    float* out = (float*)d_out;

    cudaFuncSetAttribute(deform_kernel, cudaFuncAttributeMaxDynamicSharedMemorySize, DEF_SMEM);

    prep_kernel<<<(C2 * KTOT + 255) / 256, 256>>>(w1, pw, pb, mw, mb, dw, db, w7);
    bn1_stats_kernel<<<CIN, 256>>>(x, bn1_g, bn1_b);
    xcvt_kernel<<<(BATCH * CIN * HW / 4 + 255) / 256, 256>>>(x);
    conv1_kernel<<<dim3(HW / 128, C1 / 64, BATCH), 256>>>(b1);
    bn2_stats_kernel<<<C1, 256>>>(bn2_g, bn2_b);
    pad_bn2_kernel<<<(F2TOT + 255) / 256, 256>>>();
    offconv_kernel<<<dim3(HW / 128, 1, BATCH), 256>>>();
    deform_kernel<<<dim3(HW / 128, 1, BATCH), 256, DEF_SMEM>>>(out);
}